// round 1
// baseline (speedup 1.0000x reference)
#include <cuda_runtime.h>
#include <cuda_bf16.h>
#include <math.h>

#define N_NODES 50000
#define N_EDGES 800000
#define IN_F 256
#define H_F 128
#define N_CLS 16

// ---------------- device scratch (no allocations allowed) ----------------
__device__ int   g_deg_in[N_NODES];
__device__ int   g_deg_out[N_NODES];
__device__ int   g_cursor[N_NODES];
__device__ int   g_row_off[N_NODES + 1];
__device__ int   g_edge_src[N_EDGES];
__device__ float g_norm_in[N_NODES];
__device__ float g_norm_out[N_NODES];
__device__ float g_Wt[IN_F * H_F];           // W1 transposed: [col][k]
__device__ float g_x1[N_NODES * H_F];        // (feat*norm_out) @ W1
__device__ float g_hs[N_NODES * H_F];        // relu(agg*norm_in+b1)*norm_out
__device__ float g_x2[N_NODES * N_CLS];      // g_hs @ W2

// ---------------- small setup kernels ----------------
__global__ void zero_kernel() {
    int i = blockIdx.x * blockDim.x + threadIdx.x;
    if (i < N_NODES) { g_deg_in[i] = 0; g_deg_out[i] = 0; g_cursor[i] = 0; }
}

__global__ void deg_kernel(const int* __restrict__ src, const int* __restrict__ dst) {
    int e = blockIdx.x * blockDim.x + threadIdx.x;
    if (e >= N_EDGES) return;
    atomicAdd(&g_deg_out[src[e]], 1);
    atomicAdd(&g_deg_in[dst[e]], 1);
}

__global__ void norm_kernel() {
    int i = blockIdx.x * blockDim.x + threadIdx.x;
    if (i >= N_NODES) return;
    int di = g_deg_in[i], dو = g_deg_out[i];
    g_norm_in[i]  = di > 0 ? rsqrtf((float)di) : 0.f;
    g_norm_out[i] = dو > 0 ? rsqrtf((float)dو) : 0.f;
}

// single-CTA exclusive scan of g_deg_in -> g_row_off
__global__ void scan_kernel() {
    __shared__ int sw[32];
    __shared__ int sh_carry;
    int t = threadIdx.x, lane = t & 31, wid = t >> 5;
    if (t == 0) sh_carry = 0;
    __syncthreads();
    for (int base = 0; base < N_NODES; base += 1024) {
        int i = base + t;
        int v = (i < N_NODES) ? g_deg_in[i] : 0;
        int x = v;
        #pragma unroll
        for (int o = 1; o < 32; o <<= 1) {
            int y = __shfl_up_sync(0xffffffffu, x, o);
            if (lane >= o) x += y;
        }
        if (lane == 31) sw[wid] = x;
        __syncthreads();
        if (wid == 0) {
            int s = sw[lane];
            #pragma unroll
            for (int o = 1; o < 32; o <<= 1) {
                int y = __shfl_up_sync(0xffffffffu, s, o);
                if (lane >= o) s += y;
            }
            sw[lane] = s;
        }
        __syncthreads();
        int carry = sh_carry;
        int excl = carry + (wid ? sw[wid - 1] : 0) + x - v;
        if (i < N_NODES) g_row_off[i] = excl;
        int total = carry + sw[31];
        __syncthreads();
        if (t == 0) sh_carry = total;
        __syncthreads();
    }
    if (t == 0) g_row_off[N_NODES] = sh_carry;
}

__global__ void fill_kernel(const int* __restrict__ src, const int* __restrict__ dst) {
    int e = blockIdx.x * blockDim.x + threadIdx.x;
    if (e >= N_EDGES) return;
    int d = dst[e];
    int p = atomicAdd(&g_cursor[d], 1);
    g_edge_src[g_row_off[d] + p] = src[e];
}

__global__ void transpose_kernel(const float* __restrict__ W1) {
    int t = blockIdx.x * blockDim.x + threadIdx.x;
    if (t >= IN_F * H_F) return;
    int k = t >> 7, c = t & 127;
    g_Wt[c * IN_F + k] = W1[t];
}

// ---------------- GEMM1: x1 = (feat * norm_out) @ W1  [50000 x 128] ----------------
// 128 threads/CTA, 16 rows/CTA; thread t owns output column t.
__global__ void __launch_bounds__(128) gemm1_kernel(const float* __restrict__ feat) {
    __shared__ float sA[16][IN_F];
    int t = threadIdx.x;
    int row0 = blockIdx.x * 16;
    #pragma unroll
    for (int p = 0; p < 8; p++) {
        int idx = p * 128 + t;
        int r = idx >> 6, k4 = idx & 63;
        float4 f = reinterpret_cast<const float4*>(feat)[(row0 + r) * 64 + k4];
        float nrm = g_norm_out[row0 + r];
        f.x *= nrm; f.y *= nrm; f.z *= nrm; f.w *= nrm;
        reinterpret_cast<float4*>(&sA[r][0])[k4] = f;
    }
    __syncthreads();
    float acc[16];
    #pragma unroll
    for (int r = 0; r < 16; r++) acc[r] = 0.f;
    const float4* wt = reinterpret_cast<const float4*>(g_Wt + t * IN_F);
    #pragma unroll 2
    for (int k4 = 0; k4 < 64; k4++) {
        float4 w = wt[k4];
        #pragma unroll
        for (int r = 0; r < 16; r++) {
            float4 a = reinterpret_cast<const float4*>(&sA[r][0])[k4];
            acc[r] = fmaf(a.x, w.x, acc[r]);
            acc[r] = fmaf(a.y, w.y, acc[r]);
            acc[r] = fmaf(a.z, w.z, acc[r]);
            acc[r] = fmaf(a.w, w.w, acc[r]);
        }
    }
    #pragma unroll
    for (int r = 0; r < 16; r++)
        g_x1[(row0 + r) * H_F + t] = acc[r];
}

// ---------------- Agg1: gather-sum x1 over in-edges, relu, prescale ----------------
__global__ void __launch_bounds__(128) agg1_kernel(const float* __restrict__ b1) {
    int i = blockIdx.x;
    int c = threadIdx.x;
    int beg = g_row_off[i], end = g_row_off[i + 1];
    float acc = 0.f;
    int j = beg;
    for (; j + 3 < end; j += 4) {
        int s0 = g_edge_src[j], s1 = g_edge_src[j + 1];
        int s2 = g_edge_src[j + 2], s3 = g_edge_src[j + 3];
        float v0 = g_x1[s0 * H_F + c];
        float v1 = g_x1[s1 * H_F + c];
        float v2 = g_x1[s2 * H_F + c];
        float v3 = g_x1[s3 * H_F + c];
        acc += (v0 + v1) + (v2 + v3);
    }
    for (; j < end; j++) acc += g_x1[g_edge_src[j] * H_F + c];
    float h = fmaxf(fmaf(acc, g_norm_in[i], b1[c]), 0.f);
    g_hs[i * H_F + c] = h * g_norm_out[i];
}

// ---------------- GEMM2: x2 = g_hs @ W2  [50000 x 16] ----------------
__global__ void __launch_bounds__(128) gemm2_kernel(const float* __restrict__ W2) {
    __shared__ float sW[H_F * N_CLS];
    for (int idx = threadIdx.x; idx < H_F * N_CLS; idx += 128) sW[idx] = W2[idx];
    __syncthreads();
    int r = blockIdx.x * 8 + (threadIdx.x >> 4);
    int c = threadIdx.x & 15;
    const float4* h4 = reinterpret_cast<const float4*>(g_hs + r * H_F);
    float acc = 0.f;
    #pragma unroll
    for (int k4 = 0; k4 < 32; k4++) {
        float4 hv = h4[k4];
        acc = fmaf(hv.x, sW[(k4 * 4 + 0) * N_CLS + c], acc);
        acc = fmaf(hv.y, sW[(k4 * 4 + 1) * N_CLS + c], acc);
        acc = fmaf(hv.z, sW[(k4 * 4 + 2) * N_CLS + c], acc);
        acc = fmaf(hv.w, sW[(k4 * 4 + 3) * N_CLS + c], acc);
    }
    g_x2[r * N_CLS + c] = acc;
}

// ---------------- Agg2 + bias + log_softmax -> out ----------------
__global__ void __launch_bounds__(128) agg2_kernel(const float* __restrict__ b2,
                                                   float* __restrict__ out) {
    int node = blockIdx.x * 8 + (threadIdx.x >> 4);
    int c = threadIdx.x & 15;
    int beg = g_row_off[node], end = g_row_off[node + 1];
    float acc = 0.f;
    for (int j = beg; j < end; j++) {
        int s = g_edge_src[j];
        acc += g_x2[s * N_CLS + c];
    }
    float v = fmaf(acc, g_norm_in[node], b2[c]);
    float m = v;
    #pragma unroll
    for (int o = 8; o > 0; o >>= 1)
        m = fmaxf(m, __shfl_xor_sync(0xffffffffu, m, o, 16));
    float e = expf(v - m);
    float s = e;
    #pragma unroll
    for (int o = 8; o > 0; o >>= 1)
        s += __shfl_xor_sync(0xffffffffu, s, o, 16);
    out[node * N_CLS + c] = v - m - logf(s);
}

// ---------------- launch ----------------
extern "C" void kernel_launch(void* const* d_in, const int* in_sizes, int n_in,
                              void* d_out, int out_size) {
    const float* feat = (const float*)d_in[0];
    const int*   src  = (const int*)  d_in[1];
    const int*   dst  = (const int*)  d_in[2];
    const float* W1   = (const float*)d_in[3];
    const float* b1   = (const float*)d_in[4];
    const float* W2   = (const float*)d_in[5];
    const float* b2   = (const float*)d_in[6];
    float* out = (float*)d_out;
    (void)in_sizes; (void)n_in; (void)out_size;

    zero_kernel<<<(N_NODES + 255) / 256, 256>>>();
    deg_kernel<<<(N_EDGES + 255) / 256, 256>>>(src, dst);
    norm_kernel<<<(N_NODES + 255) / 256, 256>>>();
    scan_kernel<<<1, 1024>>>();
    fill_kernel<<<(N_EDGES + 255) / 256, 256>>>(src, dst);
    transpose_kernel<<<(IN_F * H_F + 255) / 256, 256>>>(W1);
    gemm1_kernel<<<N_NODES / 16, 128>>>(feat);
    agg1_kernel<<<N_NODES, 128>>>(b1);
    gemm2_kernel<<<N_NODES / 8, 128>>>(W2);
    agg2_kernel<<<N_NODES / 8, 128>>>(b2, out);
}

// round 2
// speedup vs baseline: 1.9354x; 1.9354x over previous
#include <cuda_runtime.h>
#include <cuda_bf16.h>
#include <math.h>
#include <stdint.h>

#define N_NODES 50000
#define N_EDGES 800000
#define IN_F 256
#define H_F 128
#define N_CLS 16
#define NBLK ((N_NODES + 255) / 256)   // 196

// ---------------- device scratch (no allocations allowed) ----------------
__device__ int   g_deg_in[N_NODES];
__device__ int   g_deg_out[N_NODES];
__device__ int   g_cursor[N_NODES];
__device__ int   g_row_off[N_NODES + 1];
__device__ int   g_blk_sum[NBLK];
__device__ int   g_blk_off[NBLK];
__device__ int   g_edge_src[N_EDGES];
__device__ float g_norm_in[N_NODES];
__device__ float g_norm_out[N_NODES];
__device__ float g_x1[N_NODES * H_F];        // (feat*norm_out) @ W1
__device__ float g_hs[N_NODES * H_F];        // relu(agg*norm_in+b1)*norm_out
__device__ float g_x2[N_NODES * N_CLS];      // g_hs @ W2

// ---------------- small setup kernels ----------------
__global__ void zero_kernel() {
    int i = blockIdx.x * blockDim.x + threadIdx.x;
    if (i < N_NODES) { g_deg_in[i] = 0; g_deg_out[i] = 0; g_cursor[i] = 0; }
}

__global__ void deg_kernel(const int* __restrict__ src, const int* __restrict__ dst) {
    int e = blockIdx.x * blockDim.x + threadIdx.x;
    if (e >= N_EDGES) return;
    atomicAdd(&g_deg_out[src[e]], 1);
    atomicAdd(&g_deg_in[dst[e]], 1);
}

__global__ void norm_kernel() {
    int i = blockIdx.x * blockDim.x + threadIdx.x;
    if (i >= N_NODES) return;
    int di = g_deg_in[i], dd = g_deg_out[i];
    g_norm_in[i]  = di > 0 ? rsqrtf((float)di) : 0.f;
    g_norm_out[i] = dd > 0 ? rsqrtf((float)dd) : 0.f;
}

// ---------------- parallel scan: 3 small kernels ----------------
__global__ void scan1_kernel() {
    __shared__ int sw[8];
    int b = blockIdx.x, t = threadIdx.x;
    int i = b * 256 + t;
    int v = (i < N_NODES) ? g_deg_in[i] : 0;
    int s = v;
    #pragma unroll
    for (int o = 16; o > 0; o >>= 1) s += __shfl_xor_sync(0xffffffffu, s, o);
    if ((t & 31) == 0) sw[t >> 5] = s;
    __syncthreads();
    if (t == 0) {
        int tot = 0;
        #pragma unroll
        for (int j = 0; j < 8; j++) tot += sw[j];
        g_blk_sum[b] = tot;
    }
}

__global__ void scan2_kernel() {
    __shared__ int sw[8];
    int t = threadIdx.x, lane = t & 31, wid = t >> 5;
    int v = (t < NBLK) ? g_blk_sum[t] : 0;
    int x = v;
    #pragma unroll
    for (int o = 1; o < 32; o <<= 1) {
        int y = __shfl_up_sync(0xffffffffu, x, o);
        if (lane >= o) x += y;
    }
    if (lane == 31) sw[wid] = x;
    __syncthreads();
    if (wid == 0 && lane < 8) {
        int s = sw[lane];
        #pragma unroll
        for (int o = 1; o < 8; o <<= 1) {
            int y = __shfl_up_sync(0xffu, s, o);
            if (lane >= o) s += y;
        }
        sw[lane] = s;
    }
    __syncthreads();
    int excl = (wid ? sw[wid - 1] : 0) + x - v;
    if (t < NBLK) g_blk_off[t] = excl;
}

__global__ void scan3_kernel() {
    __shared__ int sw[8];
    int b = blockIdx.x, t = threadIdx.x, lane = t & 31, wid = t >> 5;
    int i = b * 256 + t;
    int v = (i < N_NODES) ? g_deg_in[i] : 0;
    int x = v;
    #pragma unroll
    for (int o = 1; o < 32; o <<= 1) {
        int y = __shfl_up_sync(0xffffffffu, x, o);
        if (lane >= o) x += y;
    }
    if (lane == 31) sw[wid] = x;
    __syncthreads();
    if (wid == 0 && lane < 8) {
        int s = sw[lane];
        #pragma unroll
        for (int o = 1; o < 8; o <<= 1) {
            int y = __shfl_up_sync(0xffu, s, o);
            if (lane >= o) s += y;
        }
        sw[lane] = s;
    }
    __syncthreads();
    int excl = g_blk_off[b] + (wid ? sw[wid - 1] : 0) + x - v;
    if (i < N_NODES) g_row_off[i] = excl;
    if (i == N_NODES - 1) g_row_off[N_NODES] = excl + v;
}

__global__ void fill_kernel(const int* __restrict__ src, const int* __restrict__ dst) {
    int e = blockIdx.x * blockDim.x + threadIdx.x;
    if (e >= N_EDGES) return;
    int d = dst[e];
    int p = atomicAdd(&g_cursor[d], 1);
    g_edge_src[g_row_off[d] + p] = src[e];
}

// ---------------- GEMM1 (tensor cores, tf32): x1 = (feat*norm_out) @ W1 ----------------
// CTA: 128 threads (4 warps), tile M=64, N=128. Warp tile 32x64.
// K loop: 8 chunks of 32, staged in shared with conflict-free padded strides.
__device__ __forceinline__ uint32_t f2tf32(float f) {
    uint32_t o;
    asm volatile("cvt.rna.tf32.f32 %0, %1;\n" : "=r"(o) : "f"(f));
    return o;
}

__device__ __forceinline__ void mma_tf32(float* d, const uint32_t* a, const uint32_t* b,
                                         const float* c) {
    asm volatile(
        "mma.sync.aligned.m16n8k8.row.col.f32.tf32.tf32.f32 "
        "{%0,%1,%2,%3}, {%4,%5,%6,%7}, {%8,%9}, {%10,%11,%12,%13};\n"
        : "=f"(d[0]), "=f"(d[1]), "=f"(d[2]), "=f"(d[3])
        : "r"(a[0]), "r"(a[1]), "r"(a[2]), "r"(a[3]),
          "r"(b[0]), "r"(b[1]),
          "f"(c[0]), "f"(c[1]), "f"(c[2]), "f"(c[3]));
}

#define SA_STR 36   // words; bank = (4*row + k) % 32 -> conflict-free frag loads
#define SB_STR 136  // words; bank = (8*k + col) % 32 -> conflict-free frag loads

__global__ void __launch_bounds__(128) gemm1_kernel(const float* __restrict__ feat,
                                                    const float* __restrict__ W1) {
    __shared__ uint32_t sA[64 * SA_STR];
    __shared__ uint32_t sB[32 * SB_STR];

    int t = threadIdx.x;
    int lane = t & 31, wid = t >> 5;
    int wm = wid >> 1, wn = wid & 1;           // warp tile: rows wm*32, cols wn*64
    int row0 = blockIdx.x * 64;
    int g = lane >> 2, tg = lane & 3;

    float acc[2][8][4];
    #pragma unroll
    for (int mt = 0; mt < 2; mt++)
        #pragma unroll
        for (int nt = 0; nt < 8; nt++)
            #pragma unroll
            for (int q = 0; q < 4; q++) acc[mt][nt][q] = 0.f;

    const float4* feat4 = reinterpret_cast<const float4*>(feat);
    const float4* W14   = reinterpret_cast<const float4*>(W1);

    for (int kc = 0; kc < 8; kc++) {
        // stage A chunk: 64 rows x 32 k (apply norm_out), tf32
        #pragma unroll
        for (int j = 0; j < 4; j++) {
            int idx = t + j * 128;                 // 0..511
            int r = idx >> 3, c4 = idx & 7;
            int grow = row0 + r;
            int gr = grow < N_NODES ? grow : N_NODES - 1;
            float4 f = feat4[gr * 64 + kc * 8 + c4];
            float nrm = g_norm_out[gr];
            uint32_t* dstp = &sA[r * SA_STR + c4 * 4];
            dstp[0] = f2tf32(f.x * nrm);
            dstp[1] = f2tf32(f.y * nrm);
            dstp[2] = f2tf32(f.z * nrm);
            dstp[3] = f2tf32(f.w * nrm);
        }
        // stage B chunk: 32 k x 128 n, tf32
        #pragma unroll
        for (int j = 0; j < 8; j++) {
            int idx = t + j * 128;                 // 0..1023
            int kr = idx >> 5, c4 = idx & 31;
            float4 w = W14[(kc * 32 + kr) * 32 + c4];
            uint32_t* dstp = &sB[kr * SB_STR + c4 * 4];
            dstp[0] = f2tf32(w.x);
            dstp[1] = f2tf32(w.y);
            dstp[2] = f2tf32(w.z);
            dstp[3] = f2tf32(w.w);
        }
        __syncthreads();

        #pragma unroll
        for (int ks = 0; ks < 4; ks++) {
            int kk = ks * 8 + tg;
            uint32_t a[2][4];
            #pragma unroll
            for (int mt = 0; mt < 2; mt++) {
                int r = wm * 32 + mt * 16 + g;
                a[mt][0] = sA[r * SA_STR + kk];
                a[mt][1] = sA[(r + 8) * SA_STR + kk];
                a[mt][2] = sA[r * SA_STR + kk + 4];
                a[mt][3] = sA[(r + 8) * SA_STR + kk + 4];
            }
            #pragma unroll
            for (int nt = 0; nt < 8; nt++) {
                int col = wn * 64 + nt * 8 + g;
                uint32_t b[2];
                b[0] = sB[(ks * 8 + tg) * SB_STR + col];
                b[1] = sB[(ks * 8 + tg + 4) * SB_STR + col];
                mma_tf32(acc[0][nt], a[0], b, acc[0][nt]);
                mma_tf32(acc[1][nt], a[1], b, acc[1][nt]);
            }
        }
        __syncthreads();
    }

    // epilogue
    #pragma unroll
    for (int mt = 0; mt < 2; mt++) {
        int r  = row0 + wm * 32 + mt * 16 + g;
        int r2 = r + 8;
        #pragma unroll
        for (int nt = 0; nt < 8; nt++) {
            int col = wn * 64 + nt * 8 + tg * 2;
            if (r < N_NODES) {
                float2 v = make_float2(acc[mt][nt][0], acc[mt][nt][1]);
                *reinterpret_cast<float2*>(&g_x1[r * H_F + col]) = v;
            }
            if (r2 < N_NODES) {
                float2 v = make_float2(acc[mt][nt][2], acc[mt][nt][3]);
                *reinterpret_cast<float2*>(&g_x1[r2 * H_F + col]) = v;
            }
        }
    }
}

// ---------------- Agg1: gather-sum x1 over in-edges, relu, prescale ----------------
__global__ void __launch_bounds__(128) agg1_kernel(const float* __restrict__ b1) {
    int i = blockIdx.x;
    int c = threadIdx.x;
    int beg = g_row_off[i], end = g_row_off[i + 1];
    float acc = 0.f;
    int j = beg;
    for (; j + 3 < end; j += 4) {
        int s0 = g_edge_src[j], s1 = g_edge_src[j + 1];
        int s2 = g_edge_src[j + 2], s3 = g_edge_src[j + 3];
        float v0 = g_x1[s0 * H_F + c];
        float v1 = g_x1[s1 * H_F + c];
        float v2 = g_x1[s2 * H_F + c];
        float v3 = g_x1[s3 * H_F + c];
        acc += (v0 + v1) + (v2 + v3);
    }
    for (; j < end; j++) acc += g_x1[g_edge_src[j] * H_F + c];
    float h = fmaxf(fmaf(acc, g_norm_in[i], b1[c]), 0.f);
    g_hs[i * H_F + c] = h * g_norm_out[i];
}

// ---------------- GEMM2: x2 = g_hs @ W2  [50000 x 16] ----------------
__global__ void __launch_bounds__(128) gemm2_kernel(const float* __restrict__ W2) {
    __shared__ float sW[H_F * N_CLS];
    for (int idx = threadIdx.x; idx < H_F * N_CLS; idx += 128) sW[idx] = W2[idx];
    __syncthreads();
    int r = blockIdx.x * 8 + (threadIdx.x >> 4);
    int c = threadIdx.x & 15;
    const float4* h4 = reinterpret_cast<const float4*>(g_hs + r * H_F);
    float acc = 0.f;
    #pragma unroll
    for (int k4 = 0; k4 < 32; k4++) {
        float4 hv = h4[k4];
        acc = fmaf(hv.x, sW[(k4 * 4 + 0) * N_CLS + c], acc);
        acc = fmaf(hv.y, sW[(k4 * 4 + 1) * N_CLS + c], acc);
        acc = fmaf(hv.z, sW[(k4 * 4 + 2) * N_CLS + c], acc);
        acc = fmaf(hv.w, sW[(k4 * 4 + 3) * N_CLS + c], acc);
    }
    g_x2[r * N_CLS + c] = acc;
}

// ---------------- Agg2 + bias + log_softmax -> out ----------------
__global__ void __launch_bounds__(128) agg2_kernel(const float* __restrict__ b2,
                                                   float* __restrict__ out) {
    int node = blockIdx.x * 8 + (threadIdx.x >> 4);
    int c = threadIdx.x & 15;
    int beg = g_row_off[node], end = g_row_off[node + 1];
    float acc = 0.f;
    for (int j = beg; j < end; j++) {
        int s = g_edge_src[j];
        acc += g_x2[s * N_CLS + c];
    }
    float v = fmaf(acc, g_norm_in[node], b2[c]);
    float m = v;
    #pragma unroll
    for (int o = 8; o > 0; o >>= 1)
        m = fmaxf(m, __shfl_xor_sync(0xffffffffu, m, o, 16));
    float e = expf(v - m);
    float s = e;
    #pragma unroll
    for (int o = 8; o > 0; o >>= 1)
        s += __shfl_xor_sync(0xffffffffu, s, o, 16);
    out[node * N_CLS + c] = v - m - logf(s);
}

// ---------------- launch ----------------
extern "C" void kernel_launch(void* const* d_in, const int* in_sizes, int n_in,
                              void* d_out, int out_size) {
    const float* feat = (const float*)d_in[0];
    const int*   src  = (const int*)  d_in[1];
    const int*   dst  = (const int*)  d_in[2];
    const float* W1   = (const float*)d_in[3];
    const float* b1   = (const float*)d_in[4];
    const float* W2   = (const float*)d_in[5];
    const float* b2   = (const float*)d_in[6];
    float* out = (float*)d_out;
    (void)in_sizes; (void)n_in; (void)out_size;

    zero_kernel<<<(N_NODES + 255) / 256, 256>>>();
    deg_kernel<<<(N_EDGES + 255) / 256, 256>>>(src, dst);
    norm_kernel<<<(N_NODES + 255) / 256, 256>>>();
    scan1_kernel<<<NBLK, 256>>>();
    scan2_kernel<<<1, 256>>>();
    scan3_kernel<<<NBLK, 256>>>();
    fill_kernel<<<(N_EDGES + 255) / 256, 256>>>(src, dst);
    gemm1_kernel<<<(N_NODES + 63) / 64, 128>>>(feat, W1);
    agg1_kernel<<<N_NODES, 128>>>(b1);
    gemm2_kernel<<<N_NODES / 8, 128>>>(W2);
    agg2_kernel<<<N_NODES / 8, 128>>>(b2, out);
}

// round 3
// speedup vs baseline: 1.9562x; 1.0108x over previous
#include <cuda_runtime.h>
#include <cuda_bf16.h>
#include <math.h>
#include <stdint.h>

#define N_NODES 50000
#define N_EDGES 800000
#define IN_F 256
#define H_F 128
#define N_CLS 16
#define NBLK ((N_NODES + 255) / 256)   // 196

// ---------------- device scratch (no allocations allowed) ----------------
__device__ int   g_deg_in[N_NODES];
__device__ int   g_deg_out[N_NODES];
__device__ int   g_cursor[N_NODES];
__device__ int   g_row_off[N_NODES + 1];
__device__ int   g_blk_sum[NBLK];
__device__ int   g_blk_off[NBLK];
__device__ int   g_edge_src[N_EDGES];
__device__ float g_norm_in[N_NODES];
__device__ float g_norm_out[N_NODES];
__device__ float g_x1[N_NODES * H_F];        // feat @ W1 (UNnormalized)
__device__ float g_x2[N_NODES * N_CLS];      // hs @ W2

// ---------------- setup kernels ----------------
__global__ void zero_kernel() {
    int i = blockIdx.x * blockDim.x + threadIdx.x;
    if (i < N_NODES) { g_deg_in[i] = 0; g_deg_out[i] = 0; g_cursor[i] = 0; }
}

__global__ void deg_kernel(const int* __restrict__ src, const int* __restrict__ dst) {
    int e = blockIdx.x * blockDim.x + threadIdx.x;
    if (e >= N_EDGES) return;
    atomicAdd(&g_deg_out[src[e]], 1);
    atomicAdd(&g_deg_in[dst[e]], 1);
}

// block-sum of deg_in + per-node norm computation (fused)
__global__ void scan1_kernel() {
    __shared__ int sw[8];
    int b = blockIdx.x, t = threadIdx.x;
    int i = b * 256 + t;
    int v = 0;
    if (i < N_NODES) {
        v = g_deg_in[i];
        int dd = g_deg_out[i];
        g_norm_in[i]  = v  > 0 ? rsqrtf((float)v)  : 0.f;
        g_norm_out[i] = dd > 0 ? rsqrtf((float)dd) : 0.f;
    }
    int s = v;
    #pragma unroll
    for (int o = 16; o > 0; o >>= 1) s += __shfl_xor_sync(0xffffffffu, s, o);
    if ((t & 31) == 0) sw[t >> 5] = s;
    __syncthreads();
    if (t == 0) {
        int tot = 0;
        #pragma unroll
        for (int j = 0; j < 8; j++) tot += sw[j];
        g_blk_sum[b] = tot;
    }
}

__global__ void scan2_kernel() {
    __shared__ int sw[8];
    int t = threadIdx.x, lane = t & 31, wid = t >> 5;
    int v = (t < NBLK) ? g_blk_sum[t] : 0;
    int x = v;
    #pragma unroll
    for (int o = 1; o < 32; o <<= 1) {
        int y = __shfl_up_sync(0xffffffffu, x, o);
        if (lane >= o) x += y;
    }
    if (lane == 31) sw[wid] = x;
    __syncthreads();
    if (wid == 0 && lane < 8) {
        int s = sw[lane];
        #pragma unroll
        for (int o = 1; o < 8; o <<= 1) {
            int y = __shfl_up_sync(0xffu, s, o);
            if (lane >= o) s += y;
        }
        sw[lane] = s;
    }
    __syncthreads();
    int excl = (wid ? sw[wid - 1] : 0) + x - v;
    if (t < NBLK) g_blk_off[t] = excl;
}

__global__ void scan3_kernel() {
    __shared__ int sw[8];
    int b = blockIdx.x, t = threadIdx.x, lane = t & 31, wid = t >> 5;
    int i = b * 256 + t;
    int v = (i < N_NODES) ? g_deg_in[i] : 0;
    int x = v;
    #pragma unroll
    for (int o = 1; o < 32; o <<= 1) {
        int y = __shfl_up_sync(0xffffffffu, x, o);
        if (lane >= o) x += y;
    }
    if (lane == 31) sw[wid] = x;
    __syncthreads();
    if (wid == 0 && lane < 8) {
        int s = sw[lane];
        #pragma unroll
        for (int o = 1; o < 8; o <<= 1) {
            int y = __shfl_up_sync(0xffu, s, o);
            if (lane >= o) s += y;
        }
        sw[lane] = s;
    }
    __syncthreads();
    int excl = g_blk_off[b] + (wid ? sw[wid - 1] : 0) + x - v;
    if (i < N_NODES) g_row_off[i] = excl;
    if (i == N_NODES - 1) g_row_off[N_NODES] = excl + v;
}

__global__ void fill_kernel(const int* __restrict__ src, const int* __restrict__ dst) {
    int e = blockIdx.x * blockDim.x + threadIdx.x;
    if (e >= N_EDGES) return;
    int d = dst[e];
    int p = atomicAdd(&g_cursor[d], 1);
    g_edge_src[g_row_off[d] + p] = src[e];
}

// ---------------- GEMM1 (tf32 mma, double-buffered): x1 = feat @ W1 ----------------
__device__ __forceinline__ uint32_t f2tf32(float f) {
    uint32_t o;
    asm volatile("cvt.rna.tf32.f32 %0, %1;\n" : "=r"(o) : "f"(f));
    return o;
}

__device__ __forceinline__ void mma_tf32(float* d, const uint32_t* a, const uint32_t* b,
                                         const float* c) {
    asm volatile(
        "mma.sync.aligned.m16n8k8.row.col.f32.tf32.tf32.f32 "
        "{%0,%1,%2,%3}, {%4,%5,%6,%7}, {%8,%9}, {%10,%11,%12,%13};\n"
        : "=f"(d[0]), "=f"(d[1]), "=f"(d[2]), "=f"(d[3])
        : "r"(a[0]), "r"(a[1]), "r"(a[2]), "r"(a[3]),
          "r"(b[0]), "r"(b[1]),
          "f"(c[0]), "f"(c[1]), "f"(c[2]), "f"(c[3]));
}

#define SA_STR 36    // conflict-free: bank = (4r + k) % 32
#define SB_STR 136   // conflict-free: bank = (8k + col) % 32
#define SA_WORDS (128 * SA_STR)   // 4608
#define SB_WORDS (32 * SB_STR)    // 4352
#define GEMM1_SMEM ((2 * (SA_WORDS + SB_WORDS)) * 4)  // 71680 B

__global__ void __launch_bounds__(256) gemm1_kernel(const float* __restrict__ feat,
                                                    const float* __restrict__ W1) {
    extern __shared__ uint32_t smem[];
    uint32_t* sA = smem;                       // [2][SA_WORDS]
    uint32_t* sB = smem + 2 * SA_WORDS;        // [2][SB_WORDS]

    int t = threadIdx.x;
    int lane = t & 31, wid = t >> 5;
    int wm = wid >> 1, wn = wid & 1;           // warp tile: rows wm*32, cols wn*64
    int row0 = blockIdx.x * 128;
    int g = lane >> 2, tg = lane & 3;

    float acc[2][8][4];
    #pragma unroll
    for (int mt = 0; mt < 2; mt++)
        #pragma unroll
        for (int nt = 0; nt < 8; nt++)
            #pragma unroll
            for (int q = 0; q < 4; q++) acc[mt][nt][q] = 0.f;

    const float4* feat4 = reinterpret_cast<const float4*>(feat);
    const float4* W14   = reinterpret_cast<const float4*>(W1);

    // staging coordinates (4 float4 each for A and B per thread)
    int ar[4], ac4[4], bkr[4], bc4[4];
    #pragma unroll
    for (int j = 0; j < 4; j++) {
        int idx = t + j * 256;             // 0..1023
        ar[j] = idx >> 3; ac4[j] = idx & 7;
        bkr[j] = idx >> 5; bc4[j] = idx & 31;
    }

    float4 ra[4], rb[4];
    // prologue: load chunk 0
    #pragma unroll
    for (int j = 0; j < 4; j++) {
        int grow = row0 + ar[j];
        int gr = grow < N_NODES ? grow : N_NODES - 1;
        ra[j] = feat4[gr * 64 + ac4[j]];
        rb[j] = W14[bkr[j] * 32 + bc4[j]];
    }
    #pragma unroll
    for (int j = 0; j < 4; j++) {
        uint32_t* pa = &sA[ar[j] * SA_STR + ac4[j] * 4];
        pa[0] = f2tf32(ra[j].x); pa[1] = f2tf32(ra[j].y);
        pa[2] = f2tf32(ra[j].z); pa[3] = f2tf32(ra[j].w);
        uint32_t* pb = &sB[bkr[j] * SB_STR + bc4[j] * 4];
        pb[0] = f2tf32(rb[j].x); pb[1] = f2tf32(rb[j].y);
        pb[2] = f2tf32(rb[j].z); pb[3] = f2tf32(rb[j].w);
    }
    __syncthreads();

    for (int kc = 0; kc < 8; kc++) {
        int cur = kc & 1;
        uint32_t* cA = &sA[cur * SA_WORDS];
        uint32_t* cB = &sB[cur * SB_WORDS];
        // prefetch next chunk into registers (overlaps with MMA below)
        if (kc < 7) {
            #pragma unroll
            for (int j = 0; j < 4; j++) {
                int grow = row0 + ar[j];
                int gr = grow < N_NODES ? grow : N_NODES - 1;
                ra[j] = feat4[gr * 64 + (kc + 1) * 8 + ac4[j]];
                rb[j] = W14[((kc + 1) * 32 + bkr[j]) * 32 + bc4[j]];
            }
        }
        #pragma unroll
        for (int ks = 0; ks < 4; ks++) {
            int kk = ks * 8 + tg;
            uint32_t a[2][4];
            #pragma unroll
            for (int mt = 0; mt < 2; mt++) {
                int r = wm * 32 + mt * 16 + g;
                a[mt][0] = cA[r * SA_STR + kk];
                a[mt][1] = cA[(r + 8) * SA_STR + kk];
                a[mt][2] = cA[r * SA_STR + kk + 4];
                a[mt][3] = cA[(r + 8) * SA_STR + kk + 4];
            }
            #pragma unroll
            for (int nt = 0; nt < 8; nt++) {
                int col = wn * 64 + nt * 8 + g;
                uint32_t b[2];
                b[0] = cB[kk * SB_STR + col];
                b[1] = cB[(kk + 4) * SB_STR + col];
                mma_tf32(acc[0][nt], a[0], b, acc[0][nt]);
                mma_tf32(acc[1][nt], a[1], b, acc[1][nt]);
            }
        }
        if (kc < 7) {
            uint32_t* nA = &sA[(cur ^ 1) * SA_WORDS];
            uint32_t* nB = &sB[(cur ^ 1) * SB_WORDS];
            #pragma unroll
            for (int j = 0; j < 4; j++) {
                uint32_t* pa = &nA[ar[j] * SA_STR + ac4[j] * 4];
                pa[0] = f2tf32(ra[j].x); pa[1] = f2tf32(ra[j].y);
                pa[2] = f2tf32(ra[j].z); pa[3] = f2tf32(ra[j].w);
                uint32_t* pb = &nB[bkr[j] * SB_STR + bc4[j] * 4];
                pb[0] = f2tf32(rb[j].x); pb[1] = f2tf32(rb[j].y);
                pb[2] = f2tf32(rb[j].z); pb[3] = f2tf32(rb[j].w);
            }
        }
        __syncthreads();
    }

    // epilogue (raw x@W1, no norm)
    #pragma unroll
    for (int mt = 0; mt < 2; mt++) {
        int r  = row0 + wm * 32 + mt * 16 + g;
        int r2 = r + 8;
        #pragma unroll
        for (int nt = 0; nt < 8; nt++) {
            int col = wn * 64 + nt * 8 + tg * 2;
            if (r < N_NODES)
                *reinterpret_cast<float2*>(&g_x1[r * H_F + col]) =
                    make_float2(acc[mt][nt][0], acc[mt][nt][1]);
            if (r2 < N_NODES)
                *reinterpret_cast<float2*>(&g_x1[r2 * H_F + col]) =
                    make_float2(acc[mt][nt][2], acc[mt][nt][3]);
        }
    }
}

// ---------------- fused Agg1 + ReLU + GEMM2: warp per node ----------------
// lane owns cols [4*lane, 4*lane+4). Per edge: acc4 += x1[s]*norm_out[s].
// Then h = relu(acc*norm_in + b1)*norm_out; x2 = h @ W2 via in-warp reduction.
__global__ void __launch_bounds__(128) agg1_gemm2_kernel(const float* __restrict__ b1,
                                                         const float* __restrict__ W2) {
    __shared__ float sWt[N_CLS * H_F];   // transposed: [c][k], 8KB
    for (int i = threadIdx.x; i < H_F * N_CLS; i += 128) {
        int k = i >> 4, c = i & 15;
        sWt[c * H_F + k] = W2[i];
    }
    __syncthreads();

    int warp = threadIdx.x >> 5, lane = threadIdx.x & 31;
    int node = blockIdx.x * 4 + warp;
    int beg = g_row_off[node], end = g_row_off[node + 1];

    const float4* x14 = reinterpret_cast<const float4*>(g_x1);  // row stride 32
    float4 acc = make_float4(0.f, 0.f, 0.f, 0.f);
    int j = beg;
    for (; j + 4 <= end; j += 4) {
        int s0 = g_edge_src[j],     s1 = g_edge_src[j + 1];
        int s2 = g_edge_src[j + 2], s3 = g_edge_src[j + 3];
        float n0 = g_norm_out[s0], n1 = g_norm_out[s1];
        float n2 = g_norm_out[s2], n3 = g_norm_out[s3];
        float4 v0 = x14[s0 * 32 + lane];
        float4 v1 = x14[s1 * 32 + lane];
        float4 v2 = x14[s2 * 32 + lane];
        float4 v3 = x14[s3 * 32 + lane];
        acc.x = fmaf(v0.x, n0, fmaf(v1.x, n1, fmaf(v2.x, n2, fmaf(v3.x, n3, acc.x))));
        acc.y = fmaf(v0.y, n0, fmaf(v1.y, n1, fmaf(v2.y, n2, fmaf(v3.y, n3, acc.y))));
        acc.z = fmaf(v0.z, n0, fmaf(v1.z, n1, fmaf(v2.z, n2, fmaf(v3.z, n3, acc.z))));
        acc.w = fmaf(v0.w, n0, fmaf(v1.w, n1, fmaf(v2.w, n2, fmaf(v3.w, n3, acc.w))));
    }
    for (; j < end; j++) {
        int s = g_edge_src[j];
        float n = g_norm_out[s];
        float4 v = x14[s * 32 + lane];
        acc.x = fmaf(v.x, n, acc.x);
        acc.y = fmaf(v.y, n, acc.y);
        acc.z = fmaf(v.z, n, acc.z);
        acc.w = fmaf(v.w, n, acc.w);
    }

    float ni = g_norm_in[node], no = g_norm_out[node];
    float4 bb = reinterpret_cast<const float4*>(b1)[lane];
    float4 h;
    h.x = fmaxf(fmaf(acc.x, ni, bb.x), 0.f) * no;
    h.y = fmaxf(fmaf(acc.y, ni, bb.y), 0.f) * no;
    h.z = fmaxf(fmaf(acc.z, ni, bb.z), 0.f) * no;
    h.w = fmaxf(fmaf(acc.w, ni, bb.w), 0.f) * no;

    // x2[c] = sum_k hs[k] * W2[k][c]; lane holds k = 4*lane..4*lane+3
    float p[N_CLS];
    #pragma unroll
    for (int c = 0; c < N_CLS; c++) {
        float4 w = reinterpret_cast<const float4*>(&sWt[c * H_F])[lane];
        p[c] = fmaf(h.x, w.x, fmaf(h.y, w.y, fmaf(h.z, w.z, h.w * w.w)));
    }
    #pragma unroll
    for (int o = 16; o > 0; o >>= 1) {
        #pragma unroll
        for (int c = 0; c < N_CLS; c++)
            p[c] += __shfl_xor_sync(0xffffffffu, p[c], o);
    }
    if (lane < N_CLS) g_x2[node * N_CLS + lane] = p[lane];
}

// ---------------- Agg2 + bias + log_softmax -> out ----------------
__global__ void __launch_bounds__(128) agg2_kernel(const float* __restrict__ b2,
                                                   float* __restrict__ out) {
    int node = blockIdx.x * 8 + (threadIdx.x >> 4);
    int c = threadIdx.x & 15;
    int beg = g_row_off[node], end = g_row_off[node + 1];
    float acc = 0.f;
    int j = beg;
    for (; j + 4 <= end; j += 4) {
        int s0 = g_edge_src[j],     s1 = g_edge_src[j + 1];
        int s2 = g_edge_src[j + 2], s3 = g_edge_src[j + 3];
        float v0 = g_x2[s0 * N_CLS + c];
        float v1 = g_x2[s1 * N_CLS + c];
        float v2 = g_x2[s2 * N_CLS + c];
        float v3 = g_x2[s3 * N_CLS + c];
        acc += (v0 + v1) + (v2 + v3);
    }
    for (; j < end; j++) acc += g_x2[g_edge_src[j] * N_CLS + c];
    float v = fmaf(acc, g_norm_in[node], b2[c]);
    float m = v;
    #pragma unroll
    for (int o = 8; o > 0; o >>= 1)
        m = fmaxf(m, __shfl_xor_sync(0xffffffffu, m, o, 16));
    float e = expf(v - m);
    float s = e;
    #pragma unroll
    for (int o = 8; o > 0; o >>= 1)
        s += __shfl_xor_sync(0xffffffffu, s, o, 16);
    out[node * N_CLS + c] = v - m - logf(s);
}

// ---------------- launch ----------------
extern "C" void kernel_launch(void* const* d_in, const int* in_sizes, int n_in,
                              void* d_out, int out_size) {
    const float* feat = (const float*)d_in[0];
    const int*   src  = (const int*)  d_in[1];
    const int*   dst  = (const int*)  d_in[2];
    const float* W1   = (const float*)d_in[3];
    const float* b1   = (const float*)d_in[4];
    const float* W2   = (const float*)d_in[5];
    const float* b2   = (const float*)d_in[6];
    float* out = (float*)d_out;
    (void)in_sizes; (void)n_in; (void)out_size;

    cudaFuncSetAttribute(gemm1_kernel, cudaFuncAttributeMaxDynamicSharedMemorySize,
                         GEMM1_SMEM);

    gemm1_kernel<<<(N_NODES + 127) / 128, 256, GEMM1_SMEM>>>(feat, W1);
    zero_kernel<<<(N_NODES + 255) / 256, 256>>>();
    deg_kernel<<<(N_EDGES + 255) / 256, 256>>>(src, dst);
    scan1_kernel<<<NBLK, 256>>>();
    scan2_kernel<<<1, 256>>>();
    scan3_kernel<<<NBLK, 256>>>();
    fill_kernel<<<(N_EDGES + 255) / 256, 256>>>(src, dst);
    agg1_gemm2_kernel<<<N_NODES / 4, 128>>>(b1, W2);
    agg2_kernel<<<N_NODES / 8, 128>>>(b2, out);
}

// round 5
// speedup vs baseline: 2.2560x; 1.1532x over previous
#include <cuda_runtime.h>
#include <cuda_bf16.h>
#include <math.h>
#include <stdint.h>

#define N_NODES 50000
#define N_EDGES 800000
#define IN_F 256
#define H_F 128
#define N_CLS 16
#define NBLK ((N_NODES + 255) / 256)   // 196

// ---------------- device scratch ----------------
__device__ int   g_deg_in[N_NODES];
__device__ int   g_deg_out[N_NODES];
__device__ int   g_cursor[N_NODES];
__device__ int   g_row_off[N_NODES + 1];
__device__ int   g_blk_sum[NBLK];
__device__ int   g_blk_off[NBLK];
__device__ int   g_edge_src[N_EDGES];
__device__ float g_norm_in[N_NODES];
__device__ float g_norm_out[N_NODES];
__device__ float g_x1[N_NODES * H_F];        // (feat @ W1) * norm_out[row]
__device__ float g_x2[N_NODES * N_CLS];      // hs @ W2

// ---------------- setup kernels ----------------
__global__ void zero_kernel() {
    int i = blockIdx.x * blockDim.x + threadIdx.x;
    if (i < N_NODES) { g_deg_in[i] = 0; g_deg_out[i] = 0; g_cursor[i] = 0; }
}

__global__ void deg_kernel(const int* __restrict__ src, const int* __restrict__ dst) {
    int e = blockIdx.x * blockDim.x + threadIdx.x;
    if (e >= N_EDGES) return;
    atomicAdd(&g_deg_out[src[e]], 1);
    atomicAdd(&g_deg_in[dst[e]], 1);
}

// block-sum of deg_in + norms (fused)
__global__ void scan1_kernel() {
    __shared__ int sw[8];
    int b = blockIdx.x, t = threadIdx.x;
    int i = b * 256 + t;
    int v = 0;
    if (i < N_NODES) {
        v = g_deg_in[i];
        int dd = g_deg_out[i];
        g_norm_in[i]  = v  > 0 ? rsqrtf((float)v)  : 0.f;
        g_norm_out[i] = dd > 0 ? rsqrtf((float)dd) : 0.f;
    }
    int s = v;
    #pragma unroll
    for (int o = 16; o > 0; o >>= 1) s += __shfl_xor_sync(0xffffffffu, s, o);
    if ((t & 31) == 0) sw[t >> 5] = s;
    __syncthreads();
    if (t == 0) {
        int tot = 0;
        #pragma unroll
        for (int j = 0; j < 8; j++) tot += sw[j];
        g_blk_sum[b] = tot;
    }
}

__global__ void scan2_kernel() {
    __shared__ int sw[8];
    int t = threadIdx.x, lane = t & 31, wid = t >> 5;
    int v = (t < NBLK) ? g_blk_sum[t] : 0;
    int x = v;
    #pragma unroll
    for (int o = 1; o < 32; o <<= 1) {
        int y = __shfl_up_sync(0xffffffffu, x, o);
        if (lane >= o) x += y;
    }
    if (lane == 31) sw[wid] = x;
    __syncthreads();
    if (wid == 0 && lane < 8) {
        int s = sw[lane];
        #pragma unroll
        for (int o = 1; o < 8; o <<= 1) {
            int y = __shfl_up_sync(0xffu, s, o);
            if (lane >= o) s += y;
        }
        sw[lane] = s;
    }
    __syncthreads();
    int excl = (wid ? sw[wid - 1] : 0) + x - v;
    if (t < NBLK) g_blk_off[t] = excl;
}

__global__ void scan3_kernel() {
    __shared__ int sw[8];
    int b = blockIdx.x, t = threadIdx.x, lane = t & 31, wid = t >> 5;
    int i = b * 256 + t;
    int v = (i < N_NODES) ? g_deg_in[i] : 0;
    int x = v;
    #pragma unroll
    for (int o = 1; o < 32; o <<= 1) {
        int y = __shfl_up_sync(0xffffffffu, x, o);
        if (lane >= o) x += y;
    }
    if (lane == 31) sw[wid] = x;
    __syncthreads();
    if (wid == 0 && lane < 8) {
        int s = sw[lane];
        #pragma unroll
        for (int o = 1; o < 8; o <<= 1) {
            int y = __shfl_up_sync(0xffu, s, o);
            if (lane >= o) s += y;
        }
        sw[lane] = s;
    }
    __syncthreads();
    int excl = g_blk_off[b] + (wid ? sw[wid - 1] : 0) + x - v;
    if (i < N_NODES) g_row_off[i] = excl;
    if (i == N_NODES - 1) g_row_off[N_NODES] = excl + v;
}

__global__ void fill_kernel(const int* __restrict__ src, const int* __restrict__ dst) {
    int e = blockIdx.x * blockDim.x + threadIdx.x;
    if (e >= N_EDGES) return;
    int d = dst[e];
    int p = atomicAdd(&g_cursor[d], 1);
    g_edge_src[g_row_off[d] + p] = src[e];
}

// ---------------- GEMM1 (tf32 mma + cp.async): x1 = (feat @ W1) * norm_out ----------------
__device__ __forceinline__ void mma_tf32(float* d, const uint32_t* a, const uint32_t* b,
                                         const float* c) {
    asm volatile(
        "mma.sync.aligned.m16n8k8.row.col.f32.tf32.tf32.f32 "
        "{%0,%1,%2,%3}, {%4,%5,%6,%7}, {%8,%9}, {%10,%11,%12,%13};\n"
        : "=f"(d[0]), "=f"(d[1]), "=f"(d[2]), "=f"(d[3])
        : "r"(a[0]), "r"(a[1]), "r"(a[2]), "r"(a[3]),
          "r"(b[0]), "r"(b[1]),
          "f"(c[0]), "f"(c[1]), "f"(c[2]), "f"(c[3]));
}

__device__ __forceinline__ void cp16(uint32_t saddr, const void* gptr) {
    asm volatile("cp.async.cg.shared.global [%0], [%1], 16;\n"
                 :: "r"(saddr), "l"(gptr));
}
__device__ __forceinline__ void cp_commit() {
    asm volatile("cp.async.commit_group;\n" ::: "memory");
}
__device__ __forceinline__ void cp_wait1() {
    asm volatile("cp.async.wait_group 1;\n" ::: "memory");
}

#define SA_STR 36    // conflict-free: bank = (4r + k) % 32
#define SB_STR 136   // conflict-free: bank = (8k + col) % 32
#define SA_WORDS (128 * SA_STR)
#define SB_WORDS (32 * SB_STR)
#define GEMM1_SMEM ((2 * (SA_WORDS + SB_WORDS)) * 4)

__global__ void __launch_bounds__(256) gemm1_kernel(const float* __restrict__ feat,
                                                    const float* __restrict__ W1) {
    extern __shared__ uint32_t smem[];
    uint32_t* sA = smem;
    uint32_t* sB = smem + 2 * SA_WORDS;

    int t = threadIdx.x;
    int lane = t & 31, wid = t >> 5;
    int wm = wid >> 1, wn = wid & 1;
    int row0 = blockIdx.x * 128;
    int g = lane >> 2, tg = lane & 3;

    float acc[2][8][4];
    #pragma unroll
    for (int mt = 0; mt < 2; mt++)
        #pragma unroll
        for (int nt = 0; nt < 8; nt++)
            #pragma unroll
            for (int q = 0; q < 4; q++) acc[mt][nt][q] = 0.f;

    const float4* feat4 = reinterpret_cast<const float4*>(feat);
    const float4* W14   = reinterpret_cast<const float4*>(W1);

    int ar[4], ac4[4], bkr[4], bc4[4];
    uint32_t saA[4], saB[4];
    #pragma unroll
    for (int j = 0; j < 4; j++) {
        int idx = t + j * 256;
        ar[j] = idx >> 3; ac4[j] = idx & 7;
        bkr[j] = idx >> 5; bc4[j] = idx & 31;
        saA[j] = (uint32_t)__cvta_generic_to_shared(&sA[ar[j] * SA_STR + ac4[j] * 4]);
        saB[j] = (uint32_t)__cvta_generic_to_shared(&sB[bkr[j] * SB_STR + bc4[j] * 4]);
    }
    int gr[4];
    #pragma unroll
    for (int j = 0; j < 4; j++) {
        int grow = row0 + ar[j];
        gr[j] = grow < N_NODES ? grow : N_NODES - 1;
    }

    // stage chunk 0
    #pragma unroll
    for (int j = 0; j < 4; j++) {
        cp16(saA[j], &feat4[gr[j] * 64 + ac4[j]]);
        cp16(saB[j], &W14[bkr[j] * 32 + bc4[j]]);
    }
    cp_commit();

    for (int kc = 0; kc < 8; kc++) {
        int cur = kc & 1;
        if (kc < 7) {
            int nxt = cur ^ 1;
            #pragma unroll
            for (int j = 0; j < 4; j++) {
                cp16(saA[j] + nxt * SA_WORDS * 4,
                     &feat4[gr[j] * 64 + (kc + 1) * 8 + ac4[j]]);
                cp16(saB[j] + nxt * SB_WORDS * 4,
                     &W14[((kc + 1) * 32 + bkr[j]) * 32 + bc4[j]]);
            }
            cp_commit();
        } else {
            cp_commit();  // empty group so wait_group 1 drains the real one
        }
        cp_wait1();
        __syncthreads();

        uint32_t* cA = &sA[cur * SA_WORDS];
        uint32_t* cB = &sB[cur * SB_WORDS];
        #pragma unroll
        for (int ks = 0; ks < 4; ks++) {
            int kk = ks * 8 + tg;
            uint32_t a[2][4];
            #pragma unroll
            for (int mt = 0; mt < 2; mt++) {
                int r = wm * 32 + mt * 16 + g;
                a[mt][0] = cA[r * SA_STR + kk];
                a[mt][1] = cA[(r + 8) * SA_STR + kk];
                a[mt][2] = cA[r * SA_STR + kk + 4];
                a[mt][3] = cA[(r + 8) * SA_STR + kk + 4];
            }
            #pragma unroll
            for (int nt = 0; nt < 8; nt++) {
                int col = wn * 64 + nt * 8 + g;
                uint32_t b[2];
                b[0] = cB[kk * SB_STR + col];
                b[1] = cB[(kk + 4) * SB_STR + col];
                mma_tf32(acc[0][nt], a[0], b, acc[0][nt]);
                mma_tf32(acc[1][nt], a[1], b, acc[1][nt]);
            }
        }
        __syncthreads();
    }

    // epilogue: scale rows by norm_out, store
    #pragma unroll
    for (int mt = 0; mt < 2; mt++) {
        int r  = row0 + wm * 32 + mt * 16 + g;
        int r2 = r + 8;
        float no1 = (r  < N_NODES) ? g_norm_out[r]  : 0.f;
        float no2 = (r2 < N_NODES) ? g_norm_out[r2] : 0.f;
        #pragma unroll
        for (int nt = 0; nt < 8; nt++) {
            int col = wn * 64 + nt * 8 + tg * 2;
            if (r < N_NODES)
                *reinterpret_cast<float2*>(&g_x1[r * H_F + col]) =
                    make_float2(acc[mt][nt][0] * no1, acc[mt][nt][1] * no1);
            if (r2 < N_NODES)
                *reinterpret_cast<float2*>(&g_x1[r2 * H_F + col]) =
                    make_float2(acc[mt][nt][2] * no2, acc[mt][nt][3] * no2);
        }
    }
}

// ---------------- fused Agg1 + ReLU + GEMM2: warp per node ----------------
// One node per warp => uniform trip count => full-mask shfl is safe here.
__global__ void __launch_bounds__(256) agg1_gemm2_kernel(const float* __restrict__ b1,
                                                         const float* __restrict__ W2) {
    __shared__ float sWt[N_CLS * H_F];   // transposed [c][k]
    for (int i = threadIdx.x; i < H_F * N_CLS; i += 256) {
        int k = i >> 4, c = i & 15;
        sWt[c * H_F + k] = W2[i];
    }
    __syncthreads();

    int warp = threadIdx.x >> 5, lane = threadIdx.x & 31;
    int node = blockIdx.x * 8 + warp;
    int beg = g_row_off[node], end = g_row_off[node + 1];
    int deg = end - beg;

    int v0 = (beg + lane      < end) ? g_edge_src[beg + lane]      : 0;
    int v1 = (beg + 32 + lane < end) ? g_edge_src[beg + 32 + lane] : 0;

    const float4* x14 = reinterpret_cast<const float4*>(g_x1);  // row stride 32
    float4 acc = make_float4(0.f, 0.f, 0.f, 0.f);

    int d0 = deg < 32 ? deg : 32;
    int j = 0;
    for (; j + 4 <= d0; j += 4) {
        int s0 = __shfl_sync(0xffffffffu, v0, j);
        int s1 = __shfl_sync(0xffffffffu, v0, j + 1);
        int s2 = __shfl_sync(0xffffffffu, v0, j + 2);
        int s3 = __shfl_sync(0xffffffffu, v0, j + 3);
        float4 a0 = x14[s0 * 32 + lane];
        float4 a1 = x14[s1 * 32 + lane];
        float4 a2 = x14[s2 * 32 + lane];
        float4 a3 = x14[s3 * 32 + lane];
        acc.x += (a0.x + a1.x) + (a2.x + a3.x);
        acc.y += (a0.y + a1.y) + (a2.y + a3.y);
        acc.z += (a0.z + a1.z) + (a2.z + a3.z);
        acc.w += (a0.w + a1.w) + (a2.w + a3.w);
    }
    for (; j < d0; j++) {
        int s = __shfl_sync(0xffffffffu, v0, j);
        float4 a = x14[s * 32 + lane];
        acc.x += a.x; acc.y += a.y; acc.z += a.z; acc.w += a.w;
    }
    if (deg > 32) {
        int d1 = deg - 32; if (d1 > 32) d1 = 32;
        j = 0;
        for (; j + 4 <= d1; j += 4) {
            int s0 = __shfl_sync(0xffffffffu, v1, j);
            int s1 = __shfl_sync(0xffffffffu, v1, j + 1);
            int s2 = __shfl_sync(0xffffffffu, v1, j + 2);
            int s3 = __shfl_sync(0xffffffffu, v1, j + 3);
            float4 a0 = x14[s0 * 32 + lane];
            float4 a1 = x14[s1 * 32 + lane];
            float4 a2 = x14[s2 * 32 + lane];
            float4 a3 = x14[s3 * 32 + lane];
            acc.x += (a0.x + a1.x) + (a2.x + a3.x);
            acc.y += (a0.y + a1.y) + (a2.y + a3.y);
            acc.z += (a0.z + a1.z) + (a2.z + a3.z);
            acc.w += (a0.w + a1.w) + (a2.w + a3.w);
        }
        for (; j < d1; j++) {
            int s = __shfl_sync(0xffffffffu, v1, j);
            float4 a = x14[s * 32 + lane];
            acc.x += a.x; acc.y += a.y; acc.z += a.z; acc.w += a.w;
        }
        for (int e = beg + 64; e < end; e++) {   // rare tail
            int s = g_edge_src[e];
            float4 a = x14[s * 32 + lane];
            acc.x += a.x; acc.y += a.y; acc.z += a.z; acc.w += a.w;
        }
    }

    float ni = g_norm_in[node], no = g_norm_out[node];
    float4 bb = reinterpret_cast<const float4*>(b1)[lane];
    float4 h;
    h.x = fmaxf(fmaf(acc.x, ni, bb.x), 0.f) * no;
    h.y = fmaxf(fmaf(acc.y, ni, bb.y), 0.f) * no;
    h.z = fmaxf(fmaf(acc.z, ni, bb.z), 0.f) * no;
    h.w = fmaxf(fmaf(acc.w, ni, bb.w), 0.f) * no;

    float p[N_CLS];
    #pragma unroll
    for (int c = 0; c < N_CLS; c++) {
        float4 w = reinterpret_cast<const float4*>(&sWt[c * H_F])[lane];
        p[c] = fmaf(h.x, w.x, fmaf(h.y, w.y, fmaf(h.z, w.z, h.w * w.w)));
    }
    #pragma unroll
    for (int o = 16; o > 0; o >>= 1) {
        #pragma unroll
        for (int c = 0; c < N_CLS; c++)
            p[c] += __shfl_xor_sync(0xffffffffu, p[c], o);
    }
    if (lane < N_CLS) g_x2[node * N_CLS + lane] = p[lane];
}

// ---------------- Agg2 + bias + log_softmax ----------------
// 16 lanes per node. The two half-warps have DIFFERENT degrees (divergent
// loops), so every shfl uses that half's disjoint 16-lane mask.
__global__ void __launch_bounds__(256) agg2_kernel(const float* __restrict__ b2,
                                                   float* __restrict__ out) {
    int node = blockIdx.x * 16 + (threadIdx.x >> 4);
    int c = threadIdx.x & 15;
    unsigned hm = 0xFFFFu << (((threadIdx.x >> 4) & 1) * 16);  // my half-warp mask
    int beg = g_row_off[node], end = g_row_off[node + 1];
    int deg = end - beg;

    int v0 = (beg + c      < end) ? g_edge_src[beg + c]      : 0;
    int v1 = (beg + 16 + c < end) ? g_edge_src[beg + 16 + c] : 0;
    int v2 = (beg + 32 + c < end) ? g_edge_src[beg + 32 + c] : 0;
    int v3 = (beg + 48 + c < end) ? g_edge_src[beg + 48 + c] : 0;

    float acc = 0.f;
    int dcap = deg < 64 ? deg : 64;
    for (int j = 0; j < dcap; j++) {
        int w = j >> 4, jj = j & 15;
        int s = __shfl_sync(hm, w == 0 ? v0 : w == 1 ? v1 : w == 2 ? v2 : v3, jj, 16);
        acc += g_x2[s * N_CLS + c];
    }
    for (int e = beg + 64; e < end; e++)
        acc += g_x2[g_edge_src[e] * N_CLS + c];

    float v = fmaf(acc, g_norm_in[node], b2[c]);
    float m = v;
    #pragma unroll
    for (int o = 8; o > 0; o >>= 1)
        m = fmaxf(m, __shfl_xor_sync(hm, m, o, 16));
    float e = expf(v - m);
    float s = e;
    #pragma unroll
    for (int o = 8; o > 0; o >>= 1)
        s += __shfl_xor_sync(hm, s, o, 16);
    out[node * N_CLS + c] = v - m - logf(s);
}

// ---------------- launch ----------------
extern "C" void kernel_launch(void* const* d_in, const int* in_sizes, int n_in,
                              void* d_out, int out_size) {
    const float* feat = (const float*)d_in[0];
    const int*   src  = (const int*)  d_in[1];
    const int*   dst  = (const int*)  d_in[2];
    const float* W1   = (const float*)d_in[3];
    const float* b1   = (const float*)d_in[4];
    const float* W2   = (const float*)d_in[5];
    const float* b2   = (const float*)d_in[6];
    float* out = (float*)d_out;
    (void)in_sizes; (void)n_in; (void)out_size;

    cudaFuncSetAttribute(gemm1_kernel, cudaFuncAttributeMaxDynamicSharedMemorySize,
                         GEMM1_SMEM);

    zero_kernel<<<(N_NODES + 255) / 256, 256>>>();
    deg_kernel<<<(N_EDGES + 255) / 256, 256>>>(src, dst);
    scan1_kernel<<<NBLK, 256>>>();
    scan2_kernel<<<1, 256>>>();
    scan3_kernel<<<NBLK, 256>>>();
    fill_kernel<<<(N_EDGES + 255) / 256, 256>>>(src, dst);
    gemm1_kernel<<<(N_NODES + 127) / 128, 256, GEMM1_SMEM>>>(feat, W1);
    agg1_gemm2_kernel<<<N_NODES / 8, 256>>>(b1, W2);
    agg2_kernel<<<N_NODES / 16, 256>>>(b2, out);
}

// round 6
// speedup vs baseline: 2.4104x; 1.0685x over previous
#include <cuda_runtime.h>
#include <cuda_bf16.h>
#include <cuda_fp16.h>
#include <math.h>
#include <stdint.h>

#define N_NODES 50000
#define N_EDGES 800000
#define IN_F 256
#define H_F 128
#define N_CLS 16
#define NBLK ((N_NODES + 255) / 256)   // 196

// ---------------- device scratch ----------------
__device__ int    g_deg_in[N_NODES];
__device__ int    g_deg_out[N_NODES];
__device__ int    g_cursor[N_NODES];
__device__ int    g_row_off[N_NODES + 1];
__device__ int    g_blk_sum[NBLK];
__device__ int    g_edge_src[N_EDGES];
__device__ float  g_norm_in[N_NODES];
__device__ float  g_norm_out[N_NODES];
__device__ __half g_x1h[N_NODES * H_F];      // (feat @ W1) * norm_out, fp16
__device__ float  g_x2[N_NODES * N_CLS];     // hs @ W2

// ---------------- setup kernels ----------------
__global__ void zero_kernel() {
    int i = blockIdx.x * blockDim.x + threadIdx.x;
    if (i < N_NODES) { g_deg_in[i] = 0; g_deg_out[i] = 0; g_cursor[i] = 0; }
}

__global__ void deg_kernel(const int* __restrict__ src, const int* __restrict__ dst) {
    int e = blockIdx.x * blockDim.x + threadIdx.x;
    if (e >= N_EDGES) return;
    atomicAdd(&g_deg_out[src[e]], 1);
    atomicAdd(&g_deg_in[dst[e]], 1);
}

// block-sum of deg_in + norms (fused)
__global__ void scan1_kernel() {
    __shared__ int sw[8];
    int b = blockIdx.x, t = threadIdx.x;
    int i = b * 256 + t;
    int v = 0;
    if (i < N_NODES) {
        v = g_deg_in[i];
        int dd = g_deg_out[i];
        g_norm_in[i]  = v  > 0 ? rsqrtf((float)v)  : 0.f;
        g_norm_out[i] = dd > 0 ? rsqrtf((float)dd) : 0.f;
    }
    int s = v;
    #pragma unroll
    for (int o = 16; o > 0; o >>= 1) s += __shfl_xor_sync(0xffffffffu, s, o);
    if ((t & 31) == 0) sw[t >> 5] = s;
    __syncthreads();
    if (t == 0) {
        int tot = 0;
        #pragma unroll
        for (int j = 0; j < 8; j++) tot += sw[j];
        g_blk_sum[b] = tot;
    }
}

// scan3: each CTA derives its own carry from g_blk_sum (scan2 eliminated)
__global__ void scan3_kernel() {
    __shared__ int sw[8];
    __shared__ int s_carry;
    int b = blockIdx.x, t = threadIdx.x, lane = t & 31, wid = t >> 5;

    // carry = sum of blk_sum[0..b-1] (196 values, block reduce)
    int cv = (t < NBLK && t < b) ? g_blk_sum[t] : 0;
    #pragma unroll
    for (int o = 16; o > 0; o >>= 1) cv += __shfl_xor_sync(0xffffffffu, cv, o);
    if (lane == 0) sw[wid] = cv;
    __syncthreads();
    if (t == 0) {
        int tot = 0;
        #pragma unroll
        for (int j = 0; j < 8; j++) tot += sw[j];
        s_carry = tot;
    }
    __syncthreads();
    int carry = s_carry;
    __syncthreads();   // sw reused below

    int i = b * 256 + t;
    int v = (i < N_NODES) ? g_deg_in[i] : 0;
    int x = v;
    #pragma unroll
    for (int o = 1; o < 32; o <<= 1) {
        int y = __shfl_up_sync(0xffffffffu, x, o);
        if (lane >= o) x += y;
    }
    if (lane == 31) sw[wid] = x;
    __syncthreads();
    if (wid == 0 && lane < 8) {
        int s = sw[lane];
        #pragma unroll
        for (int o = 1; o < 8; o <<= 1) {
            int y = __shfl_up_sync(0xffu, s, o);
            if (lane >= o) s += y;
        }
        sw[lane] = s;
    }
    __syncthreads();
    int excl = carry + (wid ? sw[wid - 1] : 0) + x - v;
    if (i < N_NODES) g_row_off[i] = excl;
    if (i == N_NODES - 1) g_row_off[N_NODES] = excl + v;
}

__global__ void fill_kernel(const int* __restrict__ src, const int* __restrict__ dst) {
    int e = blockIdx.x * blockDim.x + threadIdx.x;
    if (e >= N_EDGES) return;
    int d = dst[e];
    int p = atomicAdd(&g_cursor[d], 1);
    g_edge_src[g_row_off[d] + p] = src[e];
}

// ---------------- GEMM1 (tf32 mma + cp.async): x1h = half((feat @ W1) * norm_out) ----------------
__device__ __forceinline__ void mma_tf32(float* d, const uint32_t* a, const uint32_t* b,
                                         const float* c) {
    asm volatile(
        "mma.sync.aligned.m16n8k8.row.col.f32.tf32.tf32.f32 "
        "{%0,%1,%2,%3}, {%4,%5,%6,%7}, {%8,%9}, {%10,%11,%12,%13};\n"
        : "=f"(d[0]), "=f"(d[1]), "=f"(d[2]), "=f"(d[3])
        : "r"(a[0]), "r"(a[1]), "r"(a[2]), "r"(a[3]),
          "r"(b[0]), "r"(b[1]),
          "f"(c[0]), "f"(c[1]), "f"(c[2]), "f"(c[3]));
}

__device__ __forceinline__ void cp16(uint32_t saddr, const void* gptr) {
    asm volatile("cp.async.cg.shared.global [%0], [%1], 16;\n"
                 :: "r"(saddr), "l"(gptr));
}
__device__ __forceinline__ void cp_commit() {
    asm volatile("cp.async.commit_group;\n" ::: "memory");
}
__device__ __forceinline__ void cp_wait1() {
    asm volatile("cp.async.wait_group 1;\n" ::: "memory");
}

#define SA_STR 36
#define SB_STR 136
#define SA_WORDS (128 * SA_STR)
#define SB_WORDS (32 * SB_STR)
#define GEMM1_SMEM ((2 * (SA_WORDS + SB_WORDS)) * 4)

__global__ void __launch_bounds__(256) gemm1_kernel(const float* __restrict__ feat,
                                                    const float* __restrict__ W1) {
    extern __shared__ uint32_t smem[];
    uint32_t* sA = smem;
    uint32_t* sB = smem + 2 * SA_WORDS;

    int t = threadIdx.x;
    int lane = t & 31, wid = t >> 5;
    int wm = wid >> 1, wn = wid & 1;
    int row0 = blockIdx.x * 128;
    int g = lane >> 2, tg = lane & 3;

    float acc[2][8][4];
    #pragma unroll
    for (int mt = 0; mt < 2; mt++)
        #pragma unroll
        for (int nt = 0; nt < 8; nt++)
            #pragma unroll
            for (int q = 0; q < 4; q++) acc[mt][nt][q] = 0.f;

    const float4* feat4 = reinterpret_cast<const float4*>(feat);
    const float4* W14   = reinterpret_cast<const float4*>(W1);

    int ar[4], ac4[4], bkr[4], bc4[4];
    uint32_t saA[4], saB[4];
    #pragma unroll
    for (int j = 0; j < 4; j++) {
        int idx = t + j * 256;
        ar[j] = idx >> 3; ac4[j] = idx & 7;
        bkr[j] = idx >> 5; bc4[j] = idx & 31;
        saA[j] = (uint32_t)__cvta_generic_to_shared(&sA[ar[j] * SA_STR + ac4[j] * 4]);
        saB[j] = (uint32_t)__cvta_generic_to_shared(&sB[bkr[j] * SB_STR + bc4[j] * 4]);
    }
    int gr[4];
    #pragma unroll
    for (int j = 0; j < 4; j++) {
        int grow = row0 + ar[j];
        gr[j] = grow < N_NODES ? grow : N_NODES - 1;
    }

    #pragma unroll
    for (int j = 0; j < 4; j++) {
        cp16(saA[j], &feat4[gr[j] * 64 + ac4[j]]);
        cp16(saB[j], &W14[bkr[j] * 32 + bc4[j]]);
    }
    cp_commit();

    for (int kc = 0; kc < 8; kc++) {
        int cur = kc & 1;
        if (kc < 7) {
            int nxt = cur ^ 1;
            #pragma unroll
            for (int j = 0; j < 4; j++) {
                cp16(saA[j] + nxt * SA_WORDS * 4,
                     &feat4[gr[j] * 64 + (kc + 1) * 8 + ac4[j]]);
                cp16(saB[j] + nxt * SB_WORDS * 4,
                     &W14[((kc + 1) * 32 + bkr[j]) * 32 + bc4[j]]);
            }
            cp_commit();
        } else {
            cp_commit();
        }
        cp_wait1();
        __syncthreads();

        uint32_t* cA = &sA[cur * SA_WORDS];
        uint32_t* cB = &sB[cur * SB_WORDS];
        #pragma unroll
        for (int ks = 0; ks < 4; ks++) {
            int kk = ks * 8 + tg;
            uint32_t a[2][4];
            #pragma unroll
            for (int mt = 0; mt < 2; mt++) {
                int r = wm * 32 + mt * 16 + g;
                a[mt][0] = cA[r * SA_STR + kk];
                a[mt][1] = cA[(r + 8) * SA_STR + kk];
                a[mt][2] = cA[r * SA_STR + kk + 4];
                a[mt][3] = cA[(r + 8) * SA_STR + kk + 4];
            }
            #pragma unroll
            for (int nt = 0; nt < 8; nt++) {
                int col = wn * 64 + nt * 8 + g;
                uint32_t b[2];
                b[0] = cB[kk * SB_STR + col];
                b[1] = cB[(kk + 4) * SB_STR + col];
                mma_tf32(acc[0][nt], a[0], b, acc[0][nt]);
                mma_tf32(acc[1][nt], a[1], b, acc[1][nt]);
            }
        }
        __syncthreads();
    }

    // epilogue: scale by norm_out, convert fp16, store
    #pragma unroll
    for (int mt = 0; mt < 2; mt++) {
        int r  = row0 + wm * 32 + mt * 16 + g;
        int r2 = r + 8;
        float no1 = (r  < N_NODES) ? g_norm_out[r]  : 0.f;
        float no2 = (r2 < N_NODES) ? g_norm_out[r2] : 0.f;
        #pragma unroll
        for (int nt = 0; nt < 8; nt++) {
            int col = wn * 64 + nt * 8 + tg * 2;
            if (r < N_NODES)
                *reinterpret_cast<__half2*>(&g_x1h[r * H_F + col]) =
                    __floats2half2_rn(acc[mt][nt][0] * no1, acc[mt][nt][1] * no1);
            if (r2 < N_NODES)
                *reinterpret_cast<__half2*>(&g_x1h[r2 * H_F + col]) =
                    __floats2half2_rn(acc[mt][nt][2] * no2, acc[mt][nt][3] * no2);
        }
    }
}

// ---------------- fused Agg1 + ReLU + GEMM2: warp per node (fp16 gathers) ----------------
__global__ void __launch_bounds__(256) agg1_gemm2_kernel(const float* __restrict__ b1,
                                                         const float* __restrict__ W2) {
    __shared__ float sWt[N_CLS * H_F];   // transposed [c][k]
    for (int i = threadIdx.x; i < H_F * N_CLS; i += 256) {
        int k = i >> 4, c = i & 15;
        sWt[c * H_F + k] = W2[i];
    }
    __syncthreads();

    int warp = threadIdx.x >> 5, lane = threadIdx.x & 31;
    int node = blockIdx.x * 8 + warp;
    int beg = g_row_off[node], end = g_row_off[node + 1];
    int deg = end - beg;

    int v0 = (beg + lane      < end) ? g_edge_src[beg + lane]      : 0;
    int v1 = (beg + 32 + lane < end) ? g_edge_src[beg + 32 + lane] : 0;

    // lane owns cols 4*lane..4*lane+3; one uint2 (4 halves) per edge
    const uint2* x1u = reinterpret_cast<const uint2*>(g_x1h);   // row stride 32
    float2 accA = make_float2(0.f, 0.f), accB = make_float2(0.f, 0.f);

    #define ACC_EDGE(sv) do {                                          \
        uint2 u = x1u[(sv) * 32 + lane];                               \
        float2 lo = __half22float2(*reinterpret_cast<__half2*>(&u.x)); \
        float2 hi = __half22float2(*reinterpret_cast<__half2*>(&u.y)); \
        accA.x += lo.x; accA.y += lo.y; accB.x += hi.x; accB.y += hi.y;\
    } while (0)

    int d0 = deg < 32 ? deg : 32;
    int j = 0;
    for (; j + 4 <= d0; j += 4) {
        int s0 = __shfl_sync(0xffffffffu, v0, j);
        int s1 = __shfl_sync(0xffffffffu, v0, j + 1);
        int s2 = __shfl_sync(0xffffffffu, v0, j + 2);
        int s3 = __shfl_sync(0xffffffffu, v0, j + 3);
        uint2 u0 = x1u[s0 * 32 + lane];
        uint2 u1 = x1u[s1 * 32 + lane];
        uint2 u2 = x1u[s2 * 32 + lane];
        uint2 u3 = x1u[s3 * 32 + lane];
        __half2 h2a = __hadd2(*reinterpret_cast<__half2*>(&u0.x),
                              *reinterpret_cast<__half2*>(&u1.x));
        __half2 h2b = __hadd2(*reinterpret_cast<__half2*>(&u2.x),
                              *reinterpret_cast<__half2*>(&u3.x));
        __half2 h2c = __hadd2(*reinterpret_cast<__half2*>(&u0.y),
                              *reinterpret_cast<__half2*>(&u1.y));
        __half2 h2d = __hadd2(*reinterpret_cast<__half2*>(&u2.y),
                              *reinterpret_cast<__half2*>(&u3.y));
        float2 fa = __half22float2(h2a), fb = __half22float2(h2b);
        float2 fc = __half22float2(h2c), fd = __half22float2(h2d);
        accA.x += fa.x + fb.x; accA.y += fa.y + fb.y;
        accB.x += fc.x + fd.x; accB.y += fc.y + fd.y;
    }
    for (; j < d0; j++) {
        int s = __shfl_sync(0xffffffffu, v0, j);
        ACC_EDGE(s);
    }
    if (deg > 32) {
        int d1 = deg - 32; if (d1 > 32) d1 = 32;
        j = 0;
        for (; j + 4 <= d1; j += 4) {
            int s0 = __shfl_sync(0xffffffffu, v1, j);
            int s1 = __shfl_sync(0xffffffffu, v1, j + 1);
            int s2 = __shfl_sync(0xffffffffu, v1, j + 2);
            int s3 = __shfl_sync(0xffffffffu, v1, j + 3);
            ACC_EDGE(s0); ACC_EDGE(s1); ACC_EDGE(s2); ACC_EDGE(s3);
        }
        for (; j < d1; j++) {
            int s = __shfl_sync(0xffffffffu, v1, j);
            ACC_EDGE(s);
        }
        for (int e = beg + 64; e < end; e++) ACC_EDGE(g_edge_src[e]);
    }
    #undef ACC_EDGE

    float ni = g_norm_in[node], no = g_norm_out[node];
    float4 bb = reinterpret_cast<const float4*>(b1)[lane];
    float4 h;
    h.x = fmaxf(fmaf(accA.x, ni, bb.x), 0.f) * no;
    h.y = fmaxf(fmaf(accA.y, ni, bb.y), 0.f) * no;
    h.z = fmaxf(fmaf(accB.x, ni, bb.z), 0.f) * no;
    h.w = fmaxf(fmaf(accB.y, ni, bb.w), 0.f) * no;

    float p[N_CLS];
    #pragma unroll
    for (int c = 0; c < N_CLS; c++) {
        float4 w = reinterpret_cast<const float4*>(&sWt[c * H_F])[lane];
        p[c] = fmaf(h.x, w.x, fmaf(h.y, w.y, fmaf(h.z, w.z, h.w * w.w)));
    }
    #pragma unroll
    for (int o = 16; o > 0; o >>= 1) {
        #pragma unroll
        for (int c = 0; c < N_CLS; c++)
            p[c] += __shfl_xor_sync(0xffffffffu, p[c], o);
    }
    if (lane < N_CLS) g_x2[node * N_CLS + lane] = p[lane];
}

// ---------------- Agg2 + bias + log_softmax ----------------
__global__ void __launch_bounds__(256) agg2_kernel(const float* __restrict__ b2,
                                                   float* __restrict__ out) {
    int node = blockIdx.x * 16 + (threadIdx.x >> 4);
    int c = threadIdx.x & 15;
    unsigned hm = 0xFFFFu << (((threadIdx.x >> 4) & 1) * 16);
    int beg = g_row_off[node], end = g_row_off[node + 1];
    int deg = end - beg;

    int v0 = (beg + c      < end) ? g_edge_src[beg + c]      : 0;
    int v1 = (beg + 16 + c < end) ? g_edge_src[beg + 16 + c] : 0;
    int v2 = (beg + 32 + c < end) ? g_edge_src[beg + 32 + c] : 0;
    int v3 = (beg + 48 + c < end) ? g_edge_src[beg + 48 + c] : 0;

    float acc = 0.f;
    int dcap = deg < 64 ? deg : 64;
    for (int j = 0; j < dcap; j++) {
        int w = j >> 4, jj = j & 15;
        int s = __shfl_sync(hm, w == 0 ? v0 : w == 1 ? v1 : w == 2 ? v2 : v3, jj, 16);
        acc += g_x2[s * N_CLS + c];
    }
    for (int e = beg + 64; e < end; e++)
        acc += g_x2[g_edge_src[e] * N_CLS + c];

    float v = fmaf(acc, g_norm_in[node], b2[c]);
    float m = v;
    #pragma unroll
    for (int o = 8; o > 0; o >>= 1)
        m = fmaxf(m, __shfl_xor_sync(hm, m, o, 16));
    float e = expf(v - m);
    float s = e;
    #pragma unroll
    for (int o = 8; o > 0; o >>= 1)
        s += __shfl_xor_sync(hm, s, o, 16);
    out[node * N_CLS + c] = v - m - logf(s);
}

// ---------------- launch ----------------
extern "C" void kernel_launch(void* const* d_in, const int* in_sizes, int n_in,
                              void* d_out, int out_size) {
    const float* feat = (const float*)d_in[0];
    const int*   src  = (const int*)  d_in[1];
    const int*   dst  = (const int*)  d_in[2];
    const float* W1   = (const float*)d_in[3];
    const float* b1   = (const float*)d_in[4];
    const float* W2   = (const float*)d_in[5];
    const float* b2   = (const float*)d_in[6];
    float* out = (float*)d_out;
    (void)in_sizes; (void)n_in; (void)out_size;

    cudaFuncSetAttribute(gemm1_kernel, cudaFuncAttributeMaxDynamicSharedMemorySize,
                         GEMM1_SMEM);

    zero_kernel<<<(N_NODES + 255) / 256, 256>>>();
    deg_kernel<<<(N_EDGES + 255) / 256, 256>>>(src, dst);
    scan1_kernel<<<NBLK, 256>>>();
    scan3_kernel<<<NBLK, 256>>>();
    fill_kernel<<<(N_EDGES + 255) / 256, 256>>>(src, dst);
    gemm1_kernel<<<(N_NODES + 127) / 128, 256, GEMM1_SMEM>>>(feat, W1);
    agg1_gemm2_kernel<<<N_NODES / 8, 256>>>(b1, W2);
    agg2_kernel<<<N_NODES / 16, 256>>>(b2, out);
}

// round 7
// speedup vs baseline: 2.4115x; 1.0004x over previous
#include <cuda_runtime.h>
#include <cuda_bf16.h>
#include <cuda_fp16.h>
#include <math.h>
#include <stdint.h>

#define N_NODES 50000
#define N_EDGES 800000
#define IN_F 256
#define H_F 128
#define N_CLS 16
#define NBLK ((N_NODES + 255) / 256)   // 196

// ---------------- device scratch ----------------
__device__ int      g_deg_in[N_NODES];
__device__ int      g_deg_out[N_NODES];
__device__ int      g_row_off[N_NODES + 1];
__device__ int      g_blk_sum[NBLK];
__device__ int      g_slot[N_EDGES];
__device__ int      g_edge_src[N_EDGES];
__device__ float    g_norm_in[N_NODES];
__device__ float    g_norm_out[N_NODES];
__device__ __half   g_x1h[N_NODES * H_F];
__device__ float    g_x2[N_NODES * N_CLS];
__device__ unsigned g_bar_cnt;   // monotonic grid-barrier counter (never reset)

// ---------------- setup ----------------
__global__ void zero_kernel() {
    int i = blockIdx.x * blockDim.x + threadIdx.x;
    if (i < N_NODES) { g_deg_in[i] = 0; g_deg_out[i] = 0; }
}

// degrees + per-edge slot (atomic result reused => fill needs no atomics)
__global__ void deg_kernel(const int* __restrict__ src, const int* __restrict__ dst) {
    int e = blockIdx.x * blockDim.x + threadIdx.x;
    if (e >= N_EDGES) return;
    atomicAdd(&g_deg_out[src[e]], 1);
    g_slot[e] = atomicAdd(&g_deg_in[dst[e]], 1);
}

// fused scan: norms + block sums, grid barrier, then row_off
__global__ void scan_kernel() {
    __shared__ int sw[8];
    __shared__ int s_carry;
    int b = blockIdx.x, t = threadIdx.x, lane = t & 31, wid = t >> 5;
    int i = b * 256 + t;

    int v = 0;
    if (i < N_NODES) {
        v = g_deg_in[i];
        int dd = g_deg_out[i];
        g_norm_in[i]  = v  > 0 ? rsqrtf((float)v)  : 0.f;
        g_norm_out[i] = dd > 0 ? rsqrtf((float)dd) : 0.f;
    }
    // block sum
    int s = v;
    #pragma unroll
    for (int o = 16; o > 0; o >>= 1) s += __shfl_xor_sync(0xffffffffu, s, o);
    if (lane == 0) sw[wid] = s;
    __syncthreads();
    if (t == 0) {
        int tot = 0;
        #pragma unroll
        for (int j = 0; j < 8; j++) tot += sw[j];
        g_blk_sum[b] = tot;
        __threadfence();
        // monotonic grid barrier: arrivals are 196/launch
        unsigned old = atomicAdd(&g_bar_cnt, 1u);
        unsigned target = (old / NBLK + 1u) * NBLK;
        volatile unsigned* p = &g_bar_cnt;
        while (*p < target) { }
    }
    __syncthreads();
    __threadfence();

    // carry = sum blk_sum[0..b-1]
    int cv = (t < NBLK && t < b) ? g_blk_sum[t] : 0;
    #pragma unroll
    for (int o = 16; o > 0; o >>= 1) cv += __shfl_xor_sync(0xffffffffu, cv, o);
    __syncthreads();   // sw reuse
    if (lane == 0) sw[wid] = cv;
    __syncthreads();
    if (t == 0) {
        int tot = 0;
        #pragma unroll
        for (int j = 0; j < 8; j++) tot += sw[j];
        s_carry = tot;
    }
    __syncthreads();
    int carry = s_carry;
    __syncthreads();

    // local exclusive scan
    int x = v;
    #pragma unroll
    for (int o = 1; o < 32; o <<= 1) {
        int y = __shfl_up_sync(0xffffffffu, x, o);
        if (lane >= o) x += y;
    }
    if (lane == 31) sw[wid] = x;
    __syncthreads();
    if (wid == 0 && lane < 8) {
        int ss = sw[lane];
        #pragma unroll
        for (int o = 1; o < 8; o <<= 1) {
            int y = __shfl_up_sync(0xffu, ss, o);
            if (lane >= o) ss += y;
        }
        sw[lane] = ss;
    }
    __syncthreads();
    int excl = carry + (wid ? sw[wid - 1] : 0) + x - v;
    if (i < N_NODES) g_row_off[i] = excl;
    if (i == N_NODES - 1) g_row_off[N_NODES] = excl + v;
}

// atomic-free CSR fill
__global__ void fill_kernel(const int* __restrict__ src, const int* __restrict__ dst) {
    int e = blockIdx.x * blockDim.x + threadIdx.x;
    if (e >= N_EDGES) return;
    g_edge_src[g_row_off[dst[e]] + g_slot[e]] = src[e];
}

// ---------------- GEMM1 (tf32 mma + cp.async) ----------------
__device__ __forceinline__ void mma_tf32(float* d, const uint32_t* a, const uint32_t* b,
                                         const float* c) {
    asm volatile(
        "mma.sync.aligned.m16n8k8.row.col.f32.tf32.tf32.f32 "
        "{%0,%1,%2,%3}, {%4,%5,%6,%7}, {%8,%9}, {%10,%11,%12,%13};\n"
        : "=f"(d[0]), "=f"(d[1]), "=f"(d[2]), "=f"(d[3])
        : "r"(a[0]), "r"(a[1]), "r"(a[2]), "r"(a[3]),
          "r"(b[0]), "r"(b[1]),
          "f"(c[0]), "f"(c[1]), "f"(c[2]), "f"(c[3]));
}
__device__ __forceinline__ void cp16(uint32_t saddr, const void* gptr) {
    asm volatile("cp.async.cg.shared.global [%0], [%1], 16;\n" :: "r"(saddr), "l"(gptr));
}
__device__ __forceinline__ void cp_commit() {
    asm volatile("cp.async.commit_group;\n" ::: "memory");
}
__device__ __forceinline__ void cp_wait1() {
    asm volatile("cp.async.wait_group 1;\n" ::: "memory");
}

#define SA_STR 36
#define SB_STR 136
#define SA_WORDS (128 * SA_STR)
#define SB_WORDS (32 * SB_STR)
#define GEMM1_SMEM ((2 * (SA_WORDS + SB_WORDS)) * 4)

__global__ void __launch_bounds__(256) gemm1_kernel(const float* __restrict__ feat,
                                                    const float* __restrict__ W1) {
    extern __shared__ uint32_t smem[];
    uint32_t* sA = smem;
    uint32_t* sB = smem + 2 * SA_WORDS;

    int t = threadIdx.x;
    int lane = t & 31, wid = t >> 5;
    int wm = wid >> 1, wn = wid & 1;
    int row0 = blockIdx.x * 128;
    int g = lane >> 2, tg = lane & 3;

    float acc[2][8][4];
    #pragma unroll
    for (int mt = 0; mt < 2; mt++)
        #pragma unroll
        for (int nt = 0; nt < 8; nt++)
            #pragma unroll
            for (int q = 0; q < 4; q++) acc[mt][nt][q] = 0.f;

    const float4* feat4 = reinterpret_cast<const float4*>(feat);
    const float4* W14   = reinterpret_cast<const float4*>(W1);

    int ar[4], ac4[4], bkr[4], bc4[4];
    uint32_t saA[4], saB[4];
    #pragma unroll
    for (int j = 0; j < 4; j++) {
        int idx = t + j * 256;
        ar[j] = idx >> 3; ac4[j] = idx & 7;
        bkr[j] = idx >> 5; bc4[j] = idx & 31;
        saA[j] = (uint32_t)__cvta_generic_to_shared(&sA[ar[j] * SA_STR + ac4[j] * 4]);
        saB[j] = (uint32_t)__cvta_generic_to_shared(&sB[bkr[j] * SB_STR + bc4[j] * 4]);
    }
    int gr[4];
    #pragma unroll
    for (int j = 0; j < 4; j++) {
        int grow = row0 + ar[j];
        gr[j] = grow < N_NODES ? grow : N_NODES - 1;
    }

    #pragma unroll
    for (int j = 0; j < 4; j++) {
        cp16(saA[j], &feat4[gr[j] * 64 + ac4[j]]);
        cp16(saB[j], &W14[bkr[j] * 32 + bc4[j]]);
    }
    cp_commit();

    for (int kc = 0; kc < 8; kc++) {
        int cur = kc & 1;
        if (kc < 7) {
            int nxt = cur ^ 1;
            #pragma unroll
            for (int j = 0; j < 4; j++) {
                cp16(saA[j] + nxt * SA_WORDS * 4,
                     &feat4[gr[j] * 64 + (kc + 1) * 8 + ac4[j]]);
                cp16(saB[j] + nxt * SB_WORDS * 4,
                     &W14[((kc + 1) * 32 + bkr[j]) * 32 + bc4[j]]);
            }
            cp_commit();
        } else {
            cp_commit();
        }
        cp_wait1();
        __syncthreads();

        uint32_t* cA = &sA[cur * SA_WORDS];
        uint32_t* cB = &sB[cur * SB_WORDS];
        #pragma unroll
        for (int ks = 0; ks < 4; ks++) {
            int kk = ks * 8 + tg;
            uint32_t a[2][4];
            #pragma unroll
            for (int mt = 0; mt < 2; mt++) {
                int r = wm * 32 + mt * 16 + g;
                a[mt][0] = cA[r * SA_STR + kk];
                a[mt][1] = cA[(r + 8) * SA_STR + kk];
                a[mt][2] = cA[r * SA_STR + kk + 4];
                a[mt][3] = cA[(r + 8) * SA_STR + kk + 4];
            }
            #pragma unroll
            for (int nt = 0; nt < 8; nt++) {
                int col = wn * 64 + nt * 8 + g;
                uint32_t b[2];
                b[0] = cB[kk * SB_STR + col];
                b[1] = cB[(kk + 4) * SB_STR + col];
                mma_tf32(acc[0][nt], a[0], b, acc[0][nt]);
                mma_tf32(acc[1][nt], a[1], b, acc[1][nt]);
            }
        }
        __syncthreads();
    }

    #pragma unroll
    for (int mt = 0; mt < 2; mt++) {
        int r  = row0 + wm * 32 + mt * 16 + g;
        int r2 = r + 8;
        float no1 = (r  < N_NODES) ? g_norm_out[r]  : 0.f;
        float no2 = (r2 < N_NODES) ? g_norm_out[r2] : 0.f;
        #pragma unroll
        for (int nt = 0; nt < 8; nt++) {
            int col = wn * 64 + nt * 8 + tg * 2;
            if (r < N_NODES)
                *reinterpret_cast<__half2*>(&g_x1h[r * H_F + col]) =
                    __floats2half2_rn(acc[mt][nt][0] * no1, acc[mt][nt][1] * no1);
            if (r2 < N_NODES)
                *reinterpret_cast<__half2*>(&g_x1h[r2 * H_F + col]) =
                    __floats2half2_rn(acc[mt][nt][2] * no2, acc[mt][nt][3] * no2);
        }
    }
}

// ---------------- fused Agg1 + ReLU + GEMM2: warp per node, MLP-8 gathers ----------------
__global__ void __launch_bounds__(256) agg1_gemm2_kernel(const float* __restrict__ b1,
                                                         const float* __restrict__ W2) {
    __shared__ float sWt[N_CLS * H_F];
    for (int i = threadIdx.x; i < H_F * N_CLS; i += 256) {
        int k = i >> 4, c = i & 15;
        sWt[c * H_F + k] = W2[i];
    }
    __syncthreads();

    int warp = threadIdx.x >> 5, lane = threadIdx.x & 31;
    int node = blockIdx.x * 8 + warp;
    int beg = g_row_off[node], end = g_row_off[node + 1];
    int deg = end - beg;

    int v0 = (beg + lane      < end) ? g_edge_src[beg + lane]      : 0;
    int v1 = (beg + 32 + lane < end) ? g_edge_src[beg + 32 + lane] : 0;

    const uint2* x1u = reinterpret_cast<const uint2*>(g_x1h);   // row stride 32
    float2 accA = make_float2(0.f, 0.f), accB = make_float2(0.f, 0.f);

    #define ACC_U(u) do {                                               \
        float2 lo = __half22float2(*reinterpret_cast<__half2*>(&u.x));  \
        float2 hi = __half22float2(*reinterpret_cast<__half2*>(&u.y));  \
        accA.x += lo.x; accA.y += lo.y; accB.x += hi.x; accB.y += hi.y; \
    } while (0)
    #define ACC_EDGE(sv) do { uint2 u = x1u[(sv) * 32 + lane]; ACC_U(u); } while (0)

    // batch of up to 32 edges from reg vv: 8-wide independent gathers
    #define BATCH(vv, dcur) do {                                                \
        int jj = 0;                                                             \
        for (; jj + 8 <= (dcur); jj += 8) {                                     \
            int t0 = __shfl_sync(0xffffffffu, vv, jj);                          \
            int t1 = __shfl_sync(0xffffffffu, vv, jj + 1);                      \
            int t2 = __shfl_sync(0xffffffffu, vv, jj + 2);                      \
            int t3 = __shfl_sync(0xffffffffu, vv, jj + 3);                      \
            int t4 = __shfl_sync(0xffffffffu, vv, jj + 4);                      \
            int t5 = __shfl_sync(0xffffffffu, vv, jj + 5);                      \
            int t6 = __shfl_sync(0xffffffffu, vv, jj + 6);                      \
            int t7 = __shfl_sync(0xffffffffu, vv, jj + 7);                      \
            uint2 u0 = x1u[t0 * 32 + lane];                                     \
            uint2 u1 = x1u[t1 * 32 + lane];                                     \
            uint2 u2 = x1u[t2 * 32 + lane];                                     \
            uint2 u3 = x1u[t3 * 32 + lane];                                     \
            uint2 u4 = x1u[t4 * 32 + lane];                                     \
            uint2 u5 = x1u[t5 * 32 + lane];                                     \
            uint2 u6 = x1u[t6 * 32 + lane];                                     \
            uint2 u7 = x1u[t7 * 32 + lane];                                     \
            ACC_U(u0); ACC_U(u1); ACC_U(u2); ACC_U(u3);                         \
            ACC_U(u4); ACC_U(u5); ACC_U(u6); ACC_U(u7);                         \
        }                                                                       \
        for (; jj + 4 <= (dcur); jj += 4) {                                     \
            int t0 = __shfl_sync(0xffffffffu, vv, jj);                          \
            int t1 = __shfl_sync(0xffffffffu, vv, jj + 1);                      \
            int t2 = __shfl_sync(0xffffffffu, vv, jj + 2);                      \
            int t3 = __shfl_sync(0xffffffffu, vv, jj + 3);                      \
            uint2 u0 = x1u[t0 * 32 + lane];                                     \
            uint2 u1 = x1u[t1 * 32 + lane];                                     \
            uint2 u2 = x1u[t2 * 32 + lane];                                     \
            uint2 u3 = x1u[t3 * 32 + lane];                                     \
            ACC_U(u0); ACC_U(u1); ACC_U(u2); ACC_U(u3);                         \
        }                                                                       \
        for (; jj < (dcur); jj++) {                                             \
            int t0 = __shfl_sync(0xffffffffu, vv, jj);                          \
            ACC_EDGE(t0);                                                       \
        }                                                                       \
    } while (0)

    int d0 = deg < 32 ? deg : 32;
    BATCH(v0, d0);
    if (deg > 32) {
        int d1 = deg - 32; if (d1 > 32) d1 = 32;
        BATCH(v1, d1);
        for (int e = beg + 64; e < end; e++) ACC_EDGE(g_edge_src[e]);
    }
    #undef BATCH
    #undef ACC_EDGE
    #undef ACC_U

    float ni = g_norm_in[node], no = g_norm_out[node];
    float4 bb = reinterpret_cast<const float4*>(b1)[lane];
    float4 h;
    h.x = fmaxf(fmaf(accA.x, ni, bb.x), 0.f) * no;
    h.y = fmaxf(fmaf(accA.y, ni, bb.y), 0.f) * no;
    h.z = fmaxf(fmaf(accB.x, ni, bb.z), 0.f) * no;
    h.w = fmaxf(fmaf(accB.y, ni, bb.w), 0.f) * no;

    float p[N_CLS];
    #pragma unroll
    for (int c = 0; c < N_CLS; c++) {
        float4 w = reinterpret_cast<const float4*>(&sWt[c * H_F])[lane];
        p[c] = fmaf(h.x, w.x, fmaf(h.y, w.y, fmaf(h.z, w.z, h.w * w.w)));
    }
    #pragma unroll
    for (int o = 16; o > 0; o >>= 1) {
        #pragma unroll
        for (int c = 0; c < N_CLS; c++)
            p[c] += __shfl_xor_sync(0xffffffffu, p[c], o);
    }
    if (lane < N_CLS) g_x2[node * N_CLS + lane] = p[lane];
}

// ---------------- Agg2 + bias + log_softmax ----------------
__global__ void __launch_bounds__(256) agg2_kernel(const float* __restrict__ b2,
                                                   float* __restrict__ out) {
    int node = blockIdx.x * 16 + (threadIdx.x >> 4);
    int c = threadIdx.x & 15;
    unsigned hm = 0xFFFFu << (((threadIdx.x >> 4) & 1) * 16);
    int beg = g_row_off[node], end = g_row_off[node + 1];
    int deg = end - beg;

    int v0 = (beg + c      < end) ? g_edge_src[beg + c]      : 0;
    int v1 = (beg + 16 + c < end) ? g_edge_src[beg + 16 + c] : 0;
    int v2 = (beg + 32 + c < end) ? g_edge_src[beg + 32 + c] : 0;
    int v3 = (beg + 48 + c < end) ? g_edge_src[beg + 48 + c] : 0;

    float acc = 0.f;
    int dcap = deg < 64 ? deg : 64;
    for (int j = 0; j < dcap; j++) {
        int w = j >> 4, jj = j & 15;
        int s = __shfl_sync(hm, w == 0 ? v0 : w == 1 ? v1 : w == 2 ? v2 : v3, jj, 16);
        acc += g_x2[s * N_CLS + c];
    }
    for (int e = beg + 64; e < end; e++)
        acc += g_x2[g_edge_src[e] * N_CLS + c];

    float v = fmaf(acc, g_norm_in[node], b2[c]);
    float m = v;
    #pragma unroll
    for (int o = 8; o > 0; o >>= 1)
        m = fmaxf(m, __shfl_xor_sync(hm, m, o, 16));
    float e = expf(v - m);
    float s = e;
    #pragma unroll
    for (int o = 8; o > 0; o >>= 1)
        s += __shfl_xor_sync(hm, s, o, 16);
    out[node * N_CLS + c] = v - m - logf(s);
}

// ---------------- launch ----------------
extern "C" void kernel_launch(void* const* d_in, const int* in_sizes, int n_in,
                              void* d_out, int out_size) {
    const float* feat = (const float*)d_in[0];
    const int*   src  = (const int*)  d_in[1];
    const int*   dst  = (const int*)  d_in[2];
    const float* W1   = (const float*)d_in[3];
    const float* b1   = (const float*)d_in[4];
    const float* W2   = (const float*)d_in[5];
    const float* b2   = (const float*)d_in[6];
    float* out = (float*)d_out;
    (void)in_sizes; (void)n_in; (void)out_size;

    cudaFuncSetAttribute(gemm1_kernel, cudaFuncAttributeMaxDynamicSharedMemorySize,
                         GEMM1_SMEM);

    zero_kernel<<<(N_NODES + 255) / 256, 256>>>();
    deg_kernel<<<(N_EDGES + 255) / 256, 256>>>(src, dst);
    scan_kernel<<<NBLK, 256>>>();
    fill_kernel<<<(N_EDGES + 255) / 256, 256>>>(src, dst);
    gemm1_kernel<<<(N_NODES + 127) / 128, 256, GEMM1_SMEM>>>(feat, W1);
    agg1_gemm2_kernel<<<N_NODES / 8, 256>>>(b1, W2);
    agg2_kernel<<<N_NODES / 16, 256>>>(b2, out);
}

// round 8
// speedup vs baseline: 2.5652x; 1.0638x over previous
#include <cuda_runtime.h>
#include <cuda_bf16.h>
#include <cuda_fp16.h>
#include <math.h>
#include <stdint.h>

#define N_NODES 50000
#define N_EDGES 800000
#define IN_F 256
#define H_F 128
#define N_CLS 16
#define NBLK ((N_NODES + 255) / 256)   // 196
#define NPW 8                          // nodes per warp in agg1

// ---------------- device scratch ----------------
__device__ int      g_deg_in[N_NODES];
__device__ int      g_deg_out[N_NODES];
__device__ int      g_row_off[N_NODES + 1];
__device__ int      g_blk_sum[NBLK];
__device__ int      g_slot[N_EDGES];
__device__ int      g_edge_src[N_EDGES];
__device__ float    g_norm_in[N_NODES];
__device__ float    g_norm_out[N_NODES];
__device__ __half   g_x1h[N_NODES * H_F];
__device__ float    g_x2[N_NODES * N_CLS];
__device__ unsigned g_bar_cnt;   // monotonic grid-barrier counter (never reset)

// ---------------- setup ----------------
__global__ void zero_kernel() {
    int i = blockIdx.x * blockDim.x + threadIdx.x;
    if (i < N_NODES) { g_deg_in[i] = 0; g_deg_out[i] = 0; }
}

__global__ void deg_kernel(const int* __restrict__ src, const int* __restrict__ dst) {
    int e = blockIdx.x * blockDim.x + threadIdx.x;
    if (e >= N_EDGES) return;
    atomicAdd(&g_deg_out[src[e]], 1);
    g_slot[e] = atomicAdd(&g_deg_in[dst[e]], 1);
}

// fused scan: norms + block sums, grid barrier, then row_off
__global__ void scan_kernel() {
    __shared__ int sw[8];
    __shared__ int s_carry;
    int b = blockIdx.x, t = threadIdx.x, lane = t & 31, wid = t >> 5;
    int i = b * 256 + t;

    int v = 0;
    if (i < N_NODES) {
        v = g_deg_in[i];
        int dd = g_deg_out[i];
        g_norm_in[i]  = v  > 0 ? rsqrtf((float)v)  : 0.f;
        g_norm_out[i] = dd > 0 ? rsqrtf((float)dd) : 0.f;
    }
    int s = v;
    #pragma unroll
    for (int o = 16; o > 0; o >>= 1) s += __shfl_xor_sync(0xffffffffu, s, o);
    if (lane == 0) sw[wid] = s;
    __syncthreads();
    if (t == 0) {
        int tot = 0;
        #pragma unroll
        for (int j = 0; j < 8; j++) tot += sw[j];
        g_blk_sum[b] = tot;
        __threadfence();
        unsigned old = atomicAdd(&g_bar_cnt, 1u);
        unsigned target = (old / NBLK + 1u) * NBLK;
        volatile unsigned* p = &g_bar_cnt;
        while (*p < target) { }
    }
    __syncthreads();
    __threadfence();

    int cv = (t < NBLK && t < b) ? g_blk_sum[t] : 0;
    #pragma unroll
    for (int o = 16; o > 0; o >>= 1) cv += __shfl_xor_sync(0xffffffffu, cv, o);
    __syncthreads();
    if (lane == 0) sw[wid] = cv;
    __syncthreads();
    if (t == 0) {
        int tot = 0;
        #pragma unroll
        for (int j = 0; j < 8; j++) tot += sw[j];
        s_carry = tot;
    }
    __syncthreads();
    int carry = s_carry;
    __syncthreads();

    int x = v;
    #pragma unroll
    for (int o = 1; o < 32; o <<= 1) {
        int y = __shfl_up_sync(0xffffffffu, x, o);
        if (lane >= o) x += y;
    }
    if (lane == 31) sw[wid] = x;
    __syncthreads();
    if (wid == 0 && lane < 8) {
        int ss = sw[lane];
        #pragma unroll
        for (int o = 1; o < 8; o <<= 1) {
            int y = __shfl_up_sync(0xffu, ss, o);
            if (lane >= o) ss += y;
        }
        sw[lane] = ss;
    }
    __syncthreads();
    int excl = carry + (wid ? sw[wid - 1] : 0) + x - v;
    if (i < N_NODES) g_row_off[i] = excl;
    if (i == N_NODES - 1) g_row_off[N_NODES] = excl + v;
}

__global__ void fill_kernel(const int* __restrict__ src, const int* __restrict__ dst) {
    int e = blockIdx.x * blockDim.x + threadIdx.x;
    if (e >= N_EDGES) return;
    g_edge_src[g_row_off[dst[e]] + g_slot[e]] = src[e];
}

// ---------------- GEMM1 (tf32 mma + cp.async) ----------------
__device__ __forceinline__ void mma_tf32(float* d, const uint32_t* a, const uint32_t* b,
                                         const float* c) {
    asm volatile(
        "mma.sync.aligned.m16n8k8.row.col.f32.tf32.tf32.f32 "
        "{%0,%1,%2,%3}, {%4,%5,%6,%7}, {%8,%9}, {%10,%11,%12,%13};\n"
        : "=f"(d[0]), "=f"(d[1]), "=f"(d[2]), "=f"(d[3])
        : "r"(a[0]), "r"(a[1]), "r"(a[2]), "r"(a[3]),
          "r"(b[0]), "r"(b[1]),
          "f"(c[0]), "f"(c[1]), "f"(c[2]), "f"(c[3]));
}
__device__ __forceinline__ void cp16(uint32_t saddr, const void* gptr) {
    asm volatile("cp.async.cg.shared.global [%0], [%1], 16;\n" :: "r"(saddr), "l"(gptr));
}
__device__ __forceinline__ void cp_commit() {
    asm volatile("cp.async.commit_group;\n" ::: "memory");
}
__device__ __forceinline__ void cp_wait1() {
    asm volatile("cp.async.wait_group 1;\n" ::: "memory");
}

#define SA_STR 36
#define SB_STR 136
#define SA_WORDS (128 * SA_STR)
#define SB_WORDS (32 * SB_STR)
#define GEMM1_SMEM ((2 * (SA_WORDS + SB_WORDS)) * 4)

__global__ void __launch_bounds__(256) gemm1_kernel(const float* __restrict__ feat,
                                                    const float* __restrict__ W1) {
    extern __shared__ uint32_t smem[];
    uint32_t* sA = smem;
    uint32_t* sB = smem + 2 * SA_WORDS;

    int t = threadIdx.x;
    int lane = t & 31, wid = t >> 5;
    int wm = wid >> 1, wn = wid & 1;
    int row0 = blockIdx.x * 128;
    int g = lane >> 2, tg = lane & 3;

    float acc[2][8][4];
    #pragma unroll
    for (int mt = 0; mt < 2; mt++)
        #pragma unroll
        for (int nt = 0; nt < 8; nt++)
            #pragma unroll
            for (int q = 0; q < 4; q++) acc[mt][nt][q] = 0.f;

    const float4* feat4 = reinterpret_cast<const float4*>(feat);
    const float4* W14   = reinterpret_cast<const float4*>(W1);

    int ar[4], ac4[4], bkr[4], bc4[4];
    uint32_t saA[4], saB[4];
    #pragma unroll
    for (int j = 0; j < 4; j++) {
        int idx = t + j * 256;
        ar[j] = idx >> 3; ac4[j] = idx & 7;
        bkr[j] = idx >> 5; bc4[j] = idx & 31;
        saA[j] = (uint32_t)__cvta_generic_to_shared(&sA[ar[j] * SA_STR + ac4[j] * 4]);
        saB[j] = (uint32_t)__cvta_generic_to_shared(&sB[bkr[j] * SB_STR + bc4[j] * 4]);
    }
    int gr[4];
    #pragma unroll
    for (int j = 0; j < 4; j++) {
        int grow = row0 + ar[j];
        gr[j] = grow < N_NODES ? grow : N_NODES - 1;
    }

    #pragma unroll
    for (int j = 0; j < 4; j++) {
        cp16(saA[j], &feat4[gr[j] * 64 + ac4[j]]);
        cp16(saB[j], &W14[bkr[j] * 32 + bc4[j]]);
    }
    cp_commit();

    for (int kc = 0; kc < 8; kc++) {
        int cur = kc & 1;
        if (kc < 7) {
            int nxt = cur ^ 1;
            #pragma unroll
            for (int j = 0; j < 4; j++) {
                cp16(saA[j] + nxt * SA_WORDS * 4,
                     &feat4[gr[j] * 64 + (kc + 1) * 8 + ac4[j]]);
                cp16(saB[j] + nxt * SB_WORDS * 4,
                     &W14[((kc + 1) * 32 + bkr[j]) * 32 + bc4[j]]);
            }
            cp_commit();
        } else {
            cp_commit();
        }
        cp_wait1();
        __syncthreads();

        uint32_t* cA = &sA[cur * SA_WORDS];
        uint32_t* cB = &sB[cur * SB_WORDS];
        #pragma unroll
        for (int ks = 0; ks < 4; ks++) {
            int kk = ks * 8 + tg;
            uint32_t a[2][4];
            #pragma unroll
            for (int mt = 0; mt < 2; mt++) {
                int r = wm * 32 + mt * 16 + g;
                a[mt][0] = cA[r * SA_STR + kk];
                a[mt][1] = cA[(r + 8) * SA_STR + kk];
                a[mt][2] = cA[r * SA_STR + kk + 4];
                a[mt][3] = cA[(r + 8) * SA_STR + kk + 4];
            }
            #pragma unroll
            for (int nt = 0; nt < 8; nt++) {
                int col = wn * 64 + nt * 8 + g;
                uint32_t b[2];
                b[0] = cB[kk * SB_STR + col];
                b[1] = cB[(kk + 4) * SB_STR + col];
                mma_tf32(acc[0][nt], a[0], b, acc[0][nt]);
                mma_tf32(acc[1][nt], a[1], b, acc[1][nt]);
            }
        }
        __syncthreads();
    }

    #pragma unroll
    for (int mt = 0; mt < 2; mt++) {
        int r  = row0 + wm * 32 + mt * 16 + g;
        int r2 = r + 8;
        float no1 = (r  < N_NODES) ? g_norm_out[r]  : 0.f;
        float no2 = (r2 < N_NODES) ? g_norm_out[r2] : 0.f;
        #pragma unroll
        for (int nt = 0; nt < 8; nt++) {
            int col = wn * 64 + nt * 8 + tg * 2;
            if (r < N_NODES)
                *reinterpret_cast<__half2*>(&g_x1h[r * H_F + col]) =
                    __floats2half2_rn(acc[mt][nt][0] * no1, acc[mt][nt][1] * no1);
            if (r2 < N_NODES)
                *reinterpret_cast<__half2*>(&g_x1h[r2 * H_F + col]) =
                    __floats2half2_rn(acc[mt][nt][2] * no2, acc[mt][nt][3] * no2);
        }
    }
}

// ---------------- fused Agg1 + ReLU + GEMM2: 8 nodes per warp ----------------
__global__ void __launch_bounds__(256) agg1_gemm2_kernel(const float* __restrict__ b1,
                                                         const float* __restrict__ W2) {
    __shared__ float sWt[N_CLS * H_F];
    for (int i = threadIdx.x; i < H_F * N_CLS; i += 256) {
        int k = i >> 4, c = i & 15;
        sWt[c * H_F + k] = W2[i];
    }
    __syncthreads();

    int warp = threadIdx.x >> 5, lane = threadIdx.x & 31;
    int node0 = (blockIdx.x * 8 + warp) * NPW;
    const uint2* x1u = reinterpret_cast<const uint2*>(g_x1h);   // row stride 32
    float4 bb = reinterpret_cast<const float4*>(b1)[lane];
    float4 w2c[1];  // placeholder to keep compiler happy (unused)

    #define ACC_U(u) do {                                               \
        float2 lo = __half22float2(*reinterpret_cast<__half2*>(&u.x));  \
        float2 hi = __half22float2(*reinterpret_cast<__half2*>(&u.y));  \
        accA.x += lo.x; accA.y += lo.y; accB.x += hi.x; accB.y += hi.y; \
    } while (0)
    #define ACC_EDGE(sv) do { uint2 u = x1u[(sv) * 32 + lane]; ACC_U(u); } while (0)
    #define BATCH(vv, dcur) do {                                                \
        int jj = 0;                                                             \
        for (; jj + 4 <= (dcur); jj += 4) {                                     \
            int t0 = __shfl_sync(0xffffffffu, vv, jj);                          \
            int t1 = __shfl_sync(0xffffffffu, vv, jj + 1);                      \
            int t2 = __shfl_sync(0xffffffffu, vv, jj + 2);                      \
            int t3 = __shfl_sync(0xffffffffu, vv, jj + 3);                      \
            uint2 u0 = x1u[t0 * 32 + lane];                                     \
            uint2 u1 = x1u[t1 * 32 + lane];                                     \
            uint2 u2 = x1u[t2 * 32 + lane];                                     \
            uint2 u3 = x1u[t3 * 32 + lane];                                     \
            ACC_U(u0); ACC_U(u1); ACC_U(u2); ACC_U(u3);                         \
        }                                                                       \
        for (; jj < (dcur); jj++) {                                             \
            int t0 = __shfl_sync(0xffffffffu, vv, jj);                          \
            ACC_EDGE(t0);                                                       \
        }                                                                       \
    } while (0)

    #pragma unroll 1
    for (int it = 0; it < NPW; it++) {
        int node = node0 + it;
        if (node >= N_NODES) break;
        int beg = g_row_off[node], end = g_row_off[node + 1];
        int deg = end - beg;

        int v0 = (beg + lane      < end) ? g_edge_src[beg + lane]      : 0;
        int v1 = (beg + 32 + lane < end) ? g_edge_src[beg + 32 + lane] : 0;

        float2 accA = make_float2(0.f, 0.f), accB = make_float2(0.f, 0.f);

        int d0 = deg < 32 ? deg : 32;
        BATCH(v0, d0);
        if (deg > 32) {
            int d1 = deg - 32; if (d1 > 32) d1 = 32;
            BATCH(v1, d1);
            for (int e = beg + 64; e < end; e++) ACC_EDGE(g_edge_src[e]);
        }

        float ni = g_norm_in[node], no = g_norm_out[node];
        float4 h;
        h.x = fmaxf(fmaf(accA.x, ni, bb.x), 0.f) * no;
        h.y = fmaxf(fmaf(accA.y, ni, bb.y), 0.f) * no;
        h.z = fmaxf(fmaf(accB.x, ni, bb.z), 0.f) * no;
        h.w = fmaxf(fmaf(accB.y, ni, bb.w), 0.f) * no;

        float p[N_CLS];
        #pragma unroll
        for (int c = 0; c < N_CLS; c++) {
            float4 w = reinterpret_cast<const float4*>(&sWt[c * H_F])[lane];
            p[c] = fmaf(h.x, w.x, fmaf(h.y, w.y, fmaf(h.z, w.z, h.w * w.w)));
        }
        #pragma unroll
        for (int o = 16; o > 0; o >>= 1) {
            #pragma unroll
            for (int c = 0; c < N_CLS; c++)
                p[c] += __shfl_xor_sync(0xffffffffu, p[c], o);
        }
        if (lane < N_CLS) g_x2[node * N_CLS + lane] = p[lane];
    }
    #undef BATCH
    #undef ACC_EDGE
    #undef ACC_U
    (void)w2c;
}

// ---------------- Agg2 + bias + log_softmax ----------------
__global__ void __launch_bounds__(256) agg2_kernel(const float* __restrict__ b2,
                                                   float* __restrict__ out) {
    int node = blockIdx.x * 16 + (threadIdx.x >> 4);
    int c = threadIdx.x & 15;
    unsigned hm = 0xFFFFu << (((threadIdx.x >> 4) & 1) * 16);
    int beg = g_row_off[node], end = g_row_off[node + 1];
    int deg = end - beg;

    int v0 = (beg + c      < end) ? g_edge_src[beg + c]      : 0;
    int v1 = (beg + 16 + c < end) ? g_edge_src[beg + 16 + c] : 0;
    int v2 = (beg + 32 + c < end) ? g_edge_src[beg + 32 + c] : 0;
    int v3 = (beg + 48 + c < end) ? g_edge_src[beg + 48 + c] : 0;

    float acc = 0.f;
    int dcap = deg < 64 ? deg : 64;
    for (int j = 0; j < dcap; j++) {
        int w = j >> 4, jj = j & 15;
        int s = __shfl_sync(hm, w == 0 ? v0 : w == 1 ? v1 : w == 2 ? v2 : v3, jj, 16);
        acc += g_x2[s * N_CLS + c];
    }
    for (int e = beg + 64; e < end; e++)
        acc += g_x2[g_edge_src[e] * N_CLS + c];

    float v = fmaf(acc, g_norm_in[node], b2[c]);
    float m = v;
    #pragma unroll
    for (int o = 8; o > 0; o >>= 1)
        m = fmaxf(m, __shfl_xor_sync(hm, m, o, 16));
    float e = expf(v - m);
    float s = e;
    #pragma unroll
    for (int o = 8; o > 0; o >>= 1)
        s += __shfl_xor_sync(hm, s, o, 16);
    out[node * N_CLS + c] = v - m - logf(s);
}

// ---------------- launch ----------------
extern "C" void kernel_launch(void* const* d_in, const int* in_sizes, int n_in,
                              void* d_out, int out_size) {
    const float* feat = (const float*)d_in[0];
    const int*   src  = (const int*)  d_in[1];
    const int*   dst  = (const int*)  d_in[2];
    const float* W1   = (const float*)d_in[3];
    const float* b1   = (const float*)d_in[4];
    const float* W2   = (const float*)d_in[5];
    const float* b2   = (const float*)d_in[6];
    float* out = (float*)d_out;
    (void)in_sizes; (void)n_in; (void)out_size;

    cudaFuncSetAttribute(gemm1_kernel, cudaFuncAttributeMaxDynamicSharedMemorySize,
                         GEMM1_SMEM);

    zero_kernel<<<(N_NODES + 255) / 256, 256>>>();
    deg_kernel<<<(N_EDGES + 255) / 256, 256>>>(src, dst);
    scan_kernel<<<NBLK, 256>>>();
    fill_kernel<<<(N_EDGES + 255) / 256, 256>>>(src, dst);
    gemm1_kernel<<<(N_NODES + 127) / 128, 256, GEMM1_SMEM>>>(feat, W1);
    agg1_gemm2_kernel<<<(N_NODES + 8 * NPW * 8 - 1) / (8 * NPW), 256>>>(b1, W2);
    agg2_kernel<<<N_NODES / 16, 256>>>(b2, out);
}

// round 9
// speedup vs baseline: 2.6787x; 1.0442x over previous
#include <cuda_runtime.h>
#include <cuda_bf16.h>
#include <cuda_fp16.h>
#include <math.h>
#include <stdint.h>

#define N_NODES 50000
#define N_EDGES 800000
#define IN_F 256
#define H_F 128
#define N_CLS 16
#define NBLK ((N_NODES + 255) / 256)   // 196
#define NPW 8                          // nodes per warp in agg1

// ---------------- device scratch ----------------
__device__ int      g_deg_in[N_NODES];
__device__ int      g_deg_out[N_NODES];
__device__ int      g_row_off[N_NODES + 1];
__device__ int      g_blk_sum[NBLK];
__device__ int      g_slot[N_EDGES];
__device__ int      g_edge_src[N_EDGES];
__device__ float    g_norm_in[N_NODES];
__device__ float    g_norm_out[N_NODES];
__device__ __half   g_x1h[N_NODES * H_F];
__device__ float    g_x2[N_NODES * N_CLS];
__device__ unsigned g_bar_cnt;   // monotonic grid-barrier counter (never reset)

// ---------------- setup ----------------
__global__ void zero_kernel() {
    int i = blockIdx.x * blockDim.x + threadIdx.x;
    if (i < N_NODES) { g_deg_in[i] = 0; g_deg_out[i] = 0; }
}

__global__ void deg_kernel(const int* __restrict__ src, const int* __restrict__ dst) {
    int e = blockIdx.x * blockDim.x + threadIdx.x;
    if (e >= N_EDGES) return;
    atomicAdd(&g_deg_out[src[e]], 1);
    g_slot[e] = atomicAdd(&g_deg_in[dst[e]], 1);
}

// norms only (small, unblocks gemm1 early)
__global__ void norm_kernel() {
    int i = blockIdx.x * blockDim.x + threadIdx.x;
    if (i >= N_NODES) return;
    int di = g_deg_in[i], dd = g_deg_out[i];
    g_norm_in[i]  = di > 0 ? rsqrtf((float)di) : 0.f;
    g_norm_out[i] = dd > 0 ? rsqrtf((float)dd) : 0.f;
}

// fused scan: block sums, grid barrier, then row_off
__global__ void scan_kernel() {
    __shared__ int sw[8];
    __shared__ int s_carry;
    int b = blockIdx.x, t = threadIdx.x, lane = t & 31, wid = t >> 5;
    int i = b * 256 + t;

    int v = (i < N_NODES) ? g_deg_in[i] : 0;
    int s = v;
    #pragma unroll
    for (int o = 16; o > 0; o >>= 1) s += __shfl_xor_sync(0xffffffffu, s, o);
    if (lane == 0) sw[wid] = s;
    __syncthreads();
    if (t == 0) {
        int tot = 0;
        #pragma unroll
        for (int j = 0; j < 8; j++) tot += sw[j];
        g_blk_sum[b] = tot;
        __threadfence();
        unsigned old = atomicAdd(&g_bar_cnt, 1u);
        unsigned target = (old / NBLK + 1u) * NBLK;
        volatile unsigned* p = &g_bar_cnt;
        while (*p < target) { }
    }
    __syncthreads();
    __threadfence();

    int cv = (t < NBLK && t < b) ? g_blk_sum[t] : 0;
    #pragma unroll
    for (int o = 16; o > 0; o >>= 1) cv += __shfl_xor_sync(0xffffffffu, cv, o);
    __syncthreads();
    if (lane == 0) sw[wid] = cv;
    __syncthreads();
    if (t == 0) {
        int tot = 0;
        #pragma unroll
        for (int j = 0; j < 8; j++) tot += sw[j];
        s_carry = tot;
    }
    __syncthreads();
    int carry = s_carry;
    __syncthreads();

    int x = v;
    #pragma unroll
    for (int o = 1; o < 32; o <<= 1) {
        int y = __shfl_up_sync(0xffffffffu, x, o);
        if (lane >= o) x += y;
    }
    if (lane == 31) sw[wid] = x;
    __syncthreads();
    if (wid == 0 && lane < 8) {
        int ss = sw[lane];
        #pragma unroll
        for (int o = 1; o < 8; o <<= 1) {
            int y = __shfl_up_sync(0xffu, ss, o);
            if (lane >= o) ss += y;
        }
        sw[lane] = ss;
    }
    __syncthreads();
    int excl = carry + (wid ? sw[wid - 1] : 0) + x - v;
    if (i < N_NODES) g_row_off[i] = excl;
    if (i == N_NODES - 1) g_row_off[N_NODES] = excl + v;
}

__global__ void fill_kernel(const int* __restrict__ src, const int* __restrict__ dst) {
    int e = blockIdx.x * blockDim.x + threadIdx.x;
    if (e >= N_EDGES) return;
    g_edge_src[g_row_off[dst[e]] + g_slot[e]] = src[e];
}

// ---------------- GEMM1 (tf32 mma + cp.async) ----------------
__device__ __forceinline__ void mma_tf32(float* d, const uint32_t* a, const uint32_t* b,
                                         const float* c) {
    asm volatile(
        "mma.sync.aligned.m16n8k8.row.col.f32.tf32.tf32.f32 "
        "{%0,%1,%2,%3}, {%4,%5,%6,%7}, {%8,%9}, {%10,%11,%12,%13};\n"
        : "=f"(d[0]), "=f"(d[1]), "=f"(d[2]), "=f"(d[3])
        : "r"(a[0]), "r"(a[1]), "r"(a[2]), "r"(a[3]),
          "r"(b[0]), "r"(b[1]),
          "f"(c[0]), "f"(c[1]), "f"(c[2]), "f"(c[3]));
}
__device__ __forceinline__ void cp16(uint32_t saddr, const void* gptr) {
    asm volatile("cp.async.cg.shared.global [%0], [%1], 16;\n" :: "r"(saddr), "l"(gptr));
}
__device__ __forceinline__ void cp_commit() {
    asm volatile("cp.async.commit_group;\n" ::: "memory");
}
__device__ __forceinline__ void cp_wait1() {
    asm volatile("cp.async.wait_group 1;\n" ::: "memory");
}

#define SA_STR 36
#define SB_STR 136
#define SA_WORDS (128 * SA_STR)
#define SB_WORDS (32 * SB_STR)
#define GEMM1_SMEM ((2 * (SA_WORDS + SB_WORDS)) * 4)

__global__ void __launch_bounds__(256) gemm1_kernel(const float* __restrict__ feat,
                                                    const float* __restrict__ W1) {
    extern __shared__ uint32_t smem[];
    uint32_t* sA = smem;
    uint32_t* sB = smem + 2 * SA_WORDS;

    int t = threadIdx.x;
    int lane = t & 31, wid = t >> 5;
    int wm = wid >> 1, wn = wid & 1;
    int row0 = blockIdx.x * 128;
    int g = lane >> 2, tg = lane & 3;

    float acc[2][8][4];
    #pragma unroll
    for (int mt = 0; mt < 2; mt++)
        #pragma unroll
        for (int nt = 0; nt < 8; nt++)
            #pragma unroll
            for (int q = 0; q < 4; q++) acc[mt][nt][q] = 0.f;

    const float4* feat4 = reinterpret_cast<const float4*>(feat);
    const float4* W14   = reinterpret_cast<const float4*>(W1);

    int ar[4], ac4[4], bkr[4], bc4[4];
    uint32_t saA[4], saB[4];
    #pragma unroll
    for (int j = 0; j < 4; j++) {
        int idx = t + j * 256;
        ar[j] = idx >> 3; ac4[j] = idx & 7;
        bkr[j] = idx >> 5; bc4[j] = idx & 31;
        saA[j] = (uint32_t)__cvta_generic_to_shared(&sA[ar[j] * SA_STR + ac4[j] * 4]);
        saB[j] = (uint32_t)__cvta_generic_to_shared(&sB[bkr[j] * SB_STR + bc4[j] * 4]);
    }
    int gr[4];
    #pragma unroll
    for (int j = 0; j < 4; j++) {
        int grow = row0 + ar[j];
        gr[j] = grow < N_NODES ? grow : N_NODES - 1;
    }

    #pragma unroll
    for (int j = 0; j < 4; j++) {
        cp16(saA[j], &feat4[gr[j] * 64 + ac4[j]]);
        cp16(saB[j], &W14[bkr[j] * 32 + bc4[j]]);
    }
    cp_commit();

    for (int kc = 0; kc < 8; kc++) {
        int cur = kc & 1;
        if (kc < 7) {
            int nxt = cur ^ 1;
            #pragma unroll
            for (int j = 0; j < 4; j++) {
                cp16(saA[j] + nxt * SA_WORDS * 4,
                     &feat4[gr[j] * 64 + (kc + 1) * 8 + ac4[j]]);
                cp16(saB[j] + nxt * SB_WORDS * 4,
                     &W14[((kc + 1) * 32 + bkr[j]) * 32 + bc4[j]]);
            }
            cp_commit();
        } else {
            cp_commit();
        }
        cp_wait1();
        __syncthreads();

        uint32_t* cA = &sA[cur * SA_WORDS];
        uint32_t* cB = &sB[cur * SB_WORDS];
        #pragma unroll
        for (int ks = 0; ks < 4; ks++) {
            int kk = ks * 8 + tg;
            uint32_t a[2][4];
            #pragma unroll
            for (int mt = 0; mt < 2; mt++) {
                int r = wm * 32 + mt * 16 + g;
                a[mt][0] = cA[r * SA_STR + kk];
                a[mt][1] = cA[(r + 8) * SA_STR + kk];
                a[mt][2] = cA[r * SA_STR + kk + 4];
                a[mt][3] = cA[(r + 8) * SA_STR + kk + 4];
            }
            #pragma unroll
            for (int nt = 0; nt < 8; nt++) {
                int col = wn * 64 + nt * 8 + g;
                uint32_t b[2];
                b[0] = cB[kk * SB_STR + col];
                b[1] = cB[(kk + 4) * SB_STR + col];
                mma_tf32(acc[0][nt], a[0], b, acc[0][nt]);
                mma_tf32(acc[1][nt], a[1], b, acc[1][nt]);
            }
        }
        __syncthreads();
    }

    #pragma unroll
    for (int mt = 0; mt < 2; mt++) {
        int r  = row0 + wm * 32 + mt * 16 + g;
        int r2 = r + 8;
        float no1 = (r  < N_NODES) ? g_norm_out[r]  : 0.f;
        float no2 = (r2 < N_NODES) ? g_norm_out[r2] : 0.f;
        #pragma unroll
        for (int nt = 0; nt < 8; nt++) {
            int col = wn * 64 + nt * 8 + tg * 2;
            if (r < N_NODES)
                *reinterpret_cast<__half2*>(&g_x1h[r * H_F + col]) =
                    __floats2half2_rn(acc[mt][nt][0] * no1, acc[mt][nt][1] * no1);
            if (r2 < N_NODES)
                *reinterpret_cast<__half2*>(&g_x1h[r2 * H_F + col]) =
                    __floats2half2_rn(acc[mt][nt][2] * no2, acc[mt][nt][3] * no2);
        }
    }
}

// ---------------- fused Agg1 + ReLU + GEMM2: 8 nodes per warp ----------------
__global__ void __launch_bounds__(256) agg1_gemm2_kernel(const float* __restrict__ b1,
                                                         const float* __restrict__ W2) {
    __shared__ float sWt[N_CLS * H_F];
    for (int i = threadIdx.x; i < H_F * N_CLS; i += 256) {
        int k = i >> 4, c = i & 15;
        sWt[c * H_F + k] = W2[i];
    }
    __syncthreads();

    int warp = threadIdx.x >> 5, lane = threadIdx.x & 31;
    int node0 = (blockIdx.x * 8 + warp) * NPW;
    const uint2* x1u = reinterpret_cast<const uint2*>(g_x1h);   // row stride 32
    float4 bb = reinterpret_cast<const float4*>(b1)[lane];

    #define ACC_U(u) do {                                               \
        float2 lo = __half22float2(*reinterpret_cast<__half2*>(&u.x));  \
        float2 hi = __half22float2(*reinterpret_cast<__half2*>(&u.y));  \
        accA.x += lo.x; accA.y += lo.y; accB.x += hi.x; accB.y += hi.y; \
    } while (0)
    #define ACC_EDGE(sv) do { uint2 u = x1u[(sv) * 32 + lane]; ACC_U(u); } while (0)
    #define BATCH(vv, dcur) do {                                                \
        int jj = 0;                                                             \
        for (; jj + 4 <= (dcur); jj += 4) {                                     \
            int t0 = __shfl_sync(0xffffffffu, vv, jj);                          \
            int t1 = __shfl_sync(0xffffffffu, vv, jj + 1);                      \
            int t2 = __shfl_sync(0xffffffffu, vv, jj + 2);                      \
            int t3 = __shfl_sync(0xffffffffu, vv, jj + 3);                      \
            uint2 u0 = x1u[t0 * 32 + lane];                                     \
            uint2 u1 = x1u[t1 * 32 + lane];                                     \
            uint2 u2 = x1u[t2 * 32 + lane];                                     \
            uint2 u3 = x1u[t3 * 32 + lane];                                     \
            ACC_U(u0); ACC_U(u1); ACC_U(u2); ACC_U(u3);                         \
        }                                                                       \
        for (; jj < (dcur); jj++) {                                             \
            int t0 = __shfl_sync(0xffffffffu, vv, jj);                          \
            ACC_EDGE(t0);                                                       \
        }                                                                       \
    } while (0)

    #pragma unroll 1
    for (int it = 0; it < NPW; it++) {
        int node = node0 + it;
        if (node >= N_NODES) break;
        int beg = g_row_off[node], end = g_row_off[node + 1];
        int deg = end - beg;

        int v0 = (beg + lane      < end) ? g_edge_src[beg + lane]      : 0;
        int v1 = (beg + 32 + lane < end) ? g_edge_src[beg + 32 + lane] : 0;

        float2 accA = make_float2(0.f, 0.f), accB = make_float2(0.f, 0.f);

        int d0 = deg < 32 ? deg : 32;
        BATCH(v0, d0);
        if (deg > 32) {
            int d1 = deg - 32; if (d1 > 32) d1 = 32;
            BATCH(v1, d1);
            for (int e = beg + 64; e < end; e++) ACC_EDGE(g_edge_src[e]);
        }

        float ni = g_norm_in[node], no = g_norm_out[node];
        float4 h;
        h.x = fmaxf(fmaf(accA.x, ni, bb.x), 0.f) * no;
        h.y = fmaxf(fmaf(accA.y, ni, bb.y), 0.f) * no;
        h.z = fmaxf(fmaf(accB.x, ni, bb.z), 0.f) * no;
        h.w = fmaxf(fmaf(accB.y, ni, bb.w), 0.f) * no;

        float p[N_CLS];
        #pragma unroll
        for (int c = 0; c < N_CLS; c++) {
            float4 w = reinterpret_cast<const float4*>(&sWt[c * H_F])[lane];
            p[c] = fmaf(h.x, w.x, fmaf(h.y, w.y, fmaf(h.z, w.z, h.w * w.w)));
        }
        #pragma unroll
        for (int o = 16; o > 0; o >>= 1) {
            #pragma unroll
            for (int c = 0; c < N_CLS; c++)
                p[c] += __shfl_xor_sync(0xffffffffu, p[c], o);
        }
        if (lane < N_CLS) g_x2[node * N_CLS + lane] = p[lane];
    }
    #undef BATCH
    #undef ACC_EDGE
    #undef ACC_U
}

// ---------------- Agg2 + bias + log_softmax ----------------
__global__ void __launch_bounds__(256) agg2_kernel(const float* __restrict__ b2,
                                                   float* __restrict__ out) {
    int node = blockIdx.x * 16 + (threadIdx.x >> 4);
    int c = threadIdx.x & 15;
    unsigned hm = 0xFFFFu << (((threadIdx.x >> 4) & 1) * 16);
    int beg = g_row_off[node], end = g_row_off[node + 1];
    int deg = end - beg;

    int v0 = (beg + c      < end) ? g_edge_src[beg + c]      : 0;
    int v1 = (beg + 16 + c < end) ? g_edge_src[beg + 16 + c] : 0;
    int v2 = (beg + 32 + c < end) ? g_edge_src[beg + 32 + c] : 0;
    int v3 = (beg + 48 + c < end) ? g_edge_src[beg + 48 + c] : 0;

    float acc = 0.f;
    int dcap = deg < 64 ? deg : 64;
    for (int j = 0; j < dcap; j++) {
        int w = j >> 4, jj = j & 15;
        int s = __shfl_sync(hm, w == 0 ? v0 : w == 1 ? v1 : w == 2 ? v2 : v3, jj, 16);
        acc += g_x2[s * N_CLS + c];
    }
    for (int e = beg + 64; e < end; e++)
        acc += g_x2[g_edge_src[e] * N_CLS + c];

    float v = fmaf(acc, g_norm_in[node], b2[c]);
    float m = v;
    #pragma unroll
    for (int o = 8; o > 0; o >>= 1)
        m = fmaxf(m, __shfl_xor_sync(hm, m, o, 16));
    float e = expf(v - m);
    float s = e;
    #pragma unroll
    for (int o = 8; o > 0; o >>= 1)
        s += __shfl_xor_sync(hm, s, o, 16);
    out[node * N_CLS + c] = v - m - logf(s);
}

// ---------------- launch (fork/join for graph parallelism) ----------------
extern "C" void kernel_launch(void* const* d_in, const int* in_sizes, int n_in,
                              void* d_out, int out_size) {
    const float* feat = (const float*)d_in[0];
    const int*   src  = (const int*)  d_in[1];
    const int*   dst  = (const int*)  d_in[2];
    const float* W1   = (const float*)d_in[3];
    const float* b1   = (const float*)d_in[4];
    const float* W2   = (const float*)d_in[5];
    const float* b2   = (const float*)d_in[6];
    float* out = (float*)d_out;
    (void)in_sizes; (void)n_in; (void)out_size;

    // one-time host-side setup (outside capture on the first, uncaptured call)
    static cudaStream_t s2 = nullptr;
    static cudaEvent_t evFork = nullptr, evJoin = nullptr;
    if (s2 == nullptr) {
        cudaStreamCreateWithFlags(&s2, cudaStreamNonBlocking);
        cudaEventCreateWithFlags(&evFork, cudaEventDisableTiming);
        cudaEventCreateWithFlags(&evJoin, cudaEventDisableTiming);
        cudaFuncSetAttribute(gemm1_kernel, cudaFuncAttributeMaxDynamicSharedMemorySize,
                             GEMM1_SMEM);
    }

    // serial prefix: degrees + norms (gemm1's only CSR dependency)
    zero_kernel<<<(N_NODES + 255) / 256, 256>>>();
    deg_kernel<<<(N_EDGES + 255) / 256, 256>>>(src, dst);
    norm_kernel<<<(N_NODES + 255) / 256, 256>>>();

    // fork: gemm1 on s2  ||  scan+fill on default stream
    cudaEventRecord(evFork, 0);
    cudaStreamWaitEvent(s2, evFork, 0);
    gemm1_kernel<<<(N_NODES + 127) / 128, 256, GEMM1_SMEM, s2>>>(feat, W1);
    scan_kernel<<<NBLK, 256>>>();
    fill_kernel<<<(N_EDGES + 255) / 256, 256>>>(src, dst);
    cudaEventRecord(evJoin, s2);
    cudaStreamWaitEvent(0, evJoin, 0);

    // join: aggregation needs both branches
    agg1_gemm2_kernel<<<(N_NODES + 8 * NPW * 8 - 1) / (8 * NPW), 256>>>(b1, W2);
    agg2_kernel<<<N_NODES / 16, 256>>>(b2, out);
}